// round 1
// baseline (speedup 1.0000x reference)
#include <cuda_runtime.h>
#include <math.h>

#define B    128
#define H    1024
#define S    512
#define VOUT 50000
#define VIN  32000

// ---------------- persistent device scratch (no runtime allocation) ----------
__device__ float        g_inpdist[B * VIN];   // (B, V_IN) scatter-add of attn mass
__device__ int          g_winner[VOUT];       // max j with inp_to_act[j]==v, else -1
__device__ unsigned int g_rowmax[B];          // ordered-uint encoded row max of gen logits
__device__ int          g_cancopy[B];         // per-row "can copy" flag

// float <-> order-preserving uint (for atomicMax on float)
__device__ __forceinline__ unsigned int f2ord(float f) {
    unsigned int u = __float_as_uint(f);
    return (u & 0x80000000u) ? ~u : (u | 0x80000000u);
}
__device__ __forceinline__ float ord2f(unsigned int e) {
    unsigned int u = (e & 0x80000000u) ? (e & 0x7FFFFFFFu) : ~e;
    return __uint_as_float(u);
}

// ---------------- K0: reset scratch ------------------------------------------
__global__ void k_init() {
    int i = blockIdx.x * blockDim.x + threadIdx.x;
    int stride = gridDim.x * blockDim.x;
    for (int j = i; j < B * VIN; j += stride) g_inpdist[j] = 0.0f;
    for (int j = i; j < VOUT; j += stride)    g_winner[j]  = -1;
    if (i < B) { g_rowmax[i] = 0u; g_cancopy[i] = 0; }
}

// ---------------- K1: attention softmax + scatter-add into inpdist -----------
__global__ __launch_bounds__(256) void k_attn(const float* __restrict__ attn,
                                              const int*   __restrict__ inptok,
                                              float*       __restrict__ out_attn) {
    int b = blockIdx.x;
    __shared__ float red[256];
    const float* row = attn + b * S;

    float mx = -INFINITY;
    for (int s = threadIdx.x; s < S; s += 256) mx = fmaxf(mx, row[s]);
    red[threadIdx.x] = mx; __syncthreads();
    for (int off = 128; off > 0; off >>= 1) {
        if (threadIdx.x < off) red[threadIdx.x] = fmaxf(red[threadIdx.x], red[threadIdx.x + off]);
        __syncthreads();
    }
    mx = red[0]; __syncthreads();

    float sum = 0.0f;
    for (int s = threadIdx.x; s < S; s += 256) sum += expf(row[s] - mx);
    red[threadIdx.x] = sum; __syncthreads();
    for (int off = 128; off > 0; off >>= 1) {
        if (threadIdx.x < off) red[threadIdx.x] += red[threadIdx.x + off];
        __syncthreads();
    }
    sum = red[0];
    float inv = 1.0f / sum;

    for (int s = threadIdx.x; s < S; s += 256) {
        float p = expf(row[s] - mx) * inv;
        out_attn[b * S + s] = p;
        atomicAdd(&g_inpdist[b * VIN + inptok[b * S + s]], p);
    }
}

// ---------------- K2: winner index per output-vocab slot ----------------------
__global__ void k_winner(const int* __restrict__ inp_to_act) {
    int j = blockIdx.x * blockDim.x + threadIdx.x;
    if (j < VIN) atomicMax(&g_winner[inp_to_act[j]], j);
}

// ---------------- K3: GEMM gen_logits = x @ W^T + b + log(mask) --------------
// 128x128 N-tile per CTA, BK=8, 256 threads, 8x8 per thread.
#define BN 128
#define BK 8
__global__ __launch_bounds__(256) void k_gemm(const float* __restrict__ x,
                                              const float* __restrict__ W,
                                              const float* __restrict__ bias,
                                              const float* __restrict__ mask,
                                              float*       __restrict__ out_logits) {
    __shared__ float As[BK][128];
    __shared__ float Bs[BK][BN];
    int n0 = blockIdx.x * BN;
    int t  = threadIdx.x;
    int tx = t & 15, ty = t >> 4;

    float acc[8][8];
#pragma unroll
    for (int i = 0; i < 8; i++)
#pragma unroll
        for (int j = 0; j < 8; j++) acc[i][j] = 0.0f;

    int la = t >> 1;          // row within tile (0..127)
    int lk = (t & 1) * 4;     // k sub-offset (0 or 4)
    int nb = n0 + la;

    for (int k0 = 0; k0 < H; k0 += BK) {
        float4 av = *(const float4*)(x + la * H + k0 + lk);
        float4 bv = make_float4(0.f, 0.f, 0.f, 0.f);
        if (nb < VOUT) bv = *(const float4*)(W + nb * H + k0 + lk);
        __syncthreads();   // previous iteration's compute done
        As[lk + 0][la] = av.x; As[lk + 1][la] = av.y;
        As[lk + 2][la] = av.z; As[lk + 3][la] = av.w;
        Bs[lk + 0][la] = bv.x; Bs[lk + 1][la] = bv.y;
        Bs[lk + 2][la] = bv.z; Bs[lk + 3][la] = bv.w;
        __syncthreads();
#pragma unroll
        for (int kk = 0; kk < BK; kk++) {
            float a[8], bb[8];
#pragma unroll
            for (int i = 0; i < 8; i++) a[i]  = As[kk][ty * 8 + i];
#pragma unroll
            for (int j = 0; j < 8; j++) bb[j] = Bs[kk][tx * 8 + j];
#pragma unroll
            for (int i = 0; i < 8; i++)
#pragma unroll
                for (int j = 0; j < 8; j++) acc[i][j] += a[i] * bb[j];
        }
    }

    // Epilogue: bias + log(mask), write logits, row-max reduction, cancopy flag
#pragma unroll
    for (int i = 0; i < 8; i++) {
        int m = ty * 8 + i;
        float rmax = -INFINITY;
        int can = 0;
#pragma unroll
        for (int j = 0; j < 8; j++) {
            int n = n0 + tx * 8 + j;
            if (n < VOUT) {
                float om = mask[m * VOUT + n];
                float l = acc[i][j] + bias[n] + logf(om);
                out_logits[m * VOUT + n] = l;
                rmax = fmaxf(rmax, l);
                if (n != 0 && om > 0.0f && g_winner[n] >= 0) can = 1;
            }
        }
        // reduce across the 16 tx lanes (xor 1,2,4,8 stays within 16-lane half)
#pragma unroll
        for (int off = 1; off < 16; off <<= 1) {
            rmax = fmaxf(rmax, __shfl_xor_sync(0xFFFFFFFFu, rmax, off));
            can |= __shfl_xor_sync(0xFFFFFFFFu, can, off);
        }
        if (tx == 0) {
            atomicMax(&g_rowmax[m], f2ord(rmax));
            if (can) g_cancopy[m] = 1;   // idempotent store of 1
        }
    }
}

// ---------------- K4: copy-or-generate gate ----------------------------------
__global__ void k_pog(const float* __restrict__ x,
                      const float* __restrict__ cogW,
                      const float* __restrict__ cogb,
                      float*       __restrict__ out_pog) {
    int b = blockIdx.x;
    int lane = threadIdx.x;  // 32 threads
    float s0 = 0.f, s1 = 0.f;
    for (int k = lane; k < H; k += 32) {
        float xv = x[b * H + k];
        s0 += xv * cogW[k];
        s1 += xv * cogW[H + k];
    }
#pragma unroll
    for (int off = 16; off > 0; off >>= 1) {
        s0 += __shfl_xor_sync(0xFFFFFFFFu, s0, off);
        s1 += __shfl_xor_sync(0xFFFFFFFFu, s1, off);
    }
    if (lane == 0) {
        float l0 = s0 + cogb[0], l1 = s1 + cogb[1];
        int can = g_cancopy[b];
        float mx = can ? fmaxf(l0, l1) : l0;
        float e0 = expf(l0 - mx);
        float e1 = can ? expf(l1 - mx) : 0.0f;
        float inv = 1.0f / (e0 + e1);
        out_pog[2 * b]     = e0 * inv;
        out_pog[2 * b + 1] = e1 * inv;
    }
}

// ---------------- K5: row softmax over V_OUT + combine + log ------------------
__global__ __launch_bounds__(256) void k_final(float* __restrict__ logits_gen, // gen region (in: logits, out: gen_probs)
                                               float* __restrict__ out_probs,
                                               const float* __restrict__ pog) {
    int b = blockIdx.x;
    float mx = ord2f(g_rowmax[b]);
    __shared__ float red[256];
    const float* lrow = logits_gen + b * VOUT;

    float sum = 0.0f;
    for (int n = threadIdx.x; n < VOUT; n += 256) sum += expf(lrow[n] - mx);
    red[threadIdx.x] = sum; __syncthreads();
    for (int off = 128; off > 0; off >>= 1) {
        if (threadIdx.x < off) red[threadIdx.x] += red[threadIdx.x + off];
        __syncthreads();
    }
    sum = red[0];
    float inv = 1.0f / sum;
    float pg = pog[2 * b], pc = pog[2 * b + 1];

    for (int n = threadIdx.x; n < VOUT; n += 256) {
        float p = expf(lrow[n] - mx) * inv;
        int w = g_winner[n];
        float ptr = (w >= 0) ? g_inpdist[b * VIN + w] : 0.0f;
        out_probs[b * VOUT + n] = logf(pg * p + pc * ptr);
        logits_gen[b * VOUT + n] = p;   // gen_probs overwrite (same index, same thread)
    }
}

// ---------------- launch ------------------------------------------------------
extern "C" void kernel_launch(void* const* d_in, const int* in_sizes, int n_in,
                              void* d_out, int out_size) {
    const float* x          = (const float*)d_in[0];
    const int*   inptensor  = (const int*)  d_in[1];
    const float* attn       = (const float*)d_in[2];
    const float* out_mask   = (const float*)d_in[3];
    const float* gen_W      = (const float*)d_in[4];
    const float* gen_b      = (const float*)d_in[5];
    const float* cog_W      = (const float*)d_in[6];
    const float* cog_b      = (const float*)d_in[7];
    const int*   inp_to_act = (const int*)  d_in[8];

    float* out = (float*)d_out;
    // concatenated outputs: out_probs, ptr_or_gen_probs, gen_probs, attn_probs
    float* o_outprobs = out;
    float* o_pog      = out + (size_t)B * VOUT;
    float* o_gen      = o_pog + 2 * B;
    float* o_attn     = o_gen + (size_t)B * VOUT;

    k_init<<<1024, 256>>>();
    k_attn<<<B, 256>>>(attn, inptensor, o_attn);
    k_winner<<<(VIN + 255) / 256, 256>>>(inp_to_act);
    k_gemm<<<(VOUT + BN - 1) / BN, 256>>>(x, gen_W, gen_b, out_mask, o_gen);
    k_pog<<<B, 32>>>(x, cog_W, cog_b, o_pog);
    k_final<<<B, 256>>>(o_gen, o_outprobs, o_pog);
}

// round 5
// speedup vs baseline: 1.7030x; 1.7030x over previous
#include <cuda_runtime.h>
#include <cuda_bf16.h>
#include <stdint.h>
#include <math.h>

#define B    128
#define H    1024
#define S    512
#define VOUT 50000
#define VIN  32000

#define NTILE 128
#define KC    32                 // K elements per chunk
#define NCH   (H / KC)           // 32 chunks

// smem tile geometry: 128 rows x 32 bf16, row stride 80 bytes (conflict-free ldmatrix)
#define ROWB       80
#define TILE_B     (128 * ROWB)          // 10240
#define XH_OFF     0
#define XL_OFF     (1 * TILE_B)
#define WH_OFF     (2 * TILE_B)
#define WL_OFF     (3 * TILE_B)
#define BUF_B      (4 * TILE_B)          // 40960 per buffer
#define RED_OFF    (2 * BUF_B)           // 81920: u32 rowmax[128]
#define CAN_OFF    (RED_OFF + 512)       // int can[128]
#define SMEM_TOTAL (CAN_OFF + 512)       // 82944

// ---------------- persistent device scratch ----------------------------------
__device__ float        g_inpdist[B * VIN];
__device__ int          g_winner[VOUT];
__device__ unsigned int g_rowmax[B];
__device__ int          g_cancopy[B];

__device__ __forceinline__ unsigned int f2ord(float f) {
    unsigned int u = __float_as_uint(f);
    return (u & 0x80000000u) ? ~u : (u | 0x80000000u);
}
__device__ __forceinline__ float ord2f(unsigned int e) {
    unsigned int u = (e & 0x80000000u) ? (e & 0x7FFFFFFFu) : ~e;
    return __uint_as_float(u);
}

__device__ __forceinline__ uint32_t smem_u32(const void* p) {
    uint32_t a;
    asm("{ .reg .u64 t; cvta.to.shared.u64 t, %1; cvt.u32.u64 %0, t; }" : "=r"(a) : "l"(p));
    return a;
}

__device__ __forceinline__ void ldm4(uint32_t addr, uint32_t& r0, uint32_t& r1,
                                     uint32_t& r2, uint32_t& r3) {
    asm volatile("ldmatrix.sync.aligned.m8n8.x4.shared.b16 {%0,%1,%2,%3}, [%4];"
                 : "=r"(r0), "=r"(r1), "=r"(r2), "=r"(r3) : "r"(addr));
}

// address for ldmatrix.x4 over a 16x16 bf16 block at (base_row, k16) in an 80B-stride tile
__device__ __forceinline__ uint32_t ldm_addr(uint32_t tile, int base_row, int k16, int lane) {
    int mat = lane >> 3;
    int row = base_row + (lane & 7) + ((mat & 1) << 3);
    int ke  = k16 + ((mat >> 1) << 3);
    return tile + row * ROWB + ke * 2;
}

__device__ __forceinline__ void mma_bf16(float* c, const uint32_t* a, uint32_t b0, uint32_t b1) {
    asm volatile(
        "mma.sync.aligned.m16n8k16.row.col.f32.bf16.bf16.f32 "
        "{%0,%1,%2,%3}, {%4,%5,%6,%7}, {%8,%9}, {%0,%1,%2,%3};"
        : "+f"(c[0]), "+f"(c[1]), "+f"(c[2]), "+f"(c[3])
        : "r"(a[0]), "r"(a[1]), "r"(a[2]), "r"(a[3]), "r"(b0), "r"(b1));
}

// fp32x4 -> bf16 hi (2xb32) + bf16 lo-residual (2xb32), stored to smem
__device__ __forceinline__ void cvtstore(uint32_t hi_addr, uint32_t lo_addr, float4 v) {
    float f[4] = {v.x, v.y, v.z, v.w};
    unsigned h[4], l[4];
#pragma unroll
    for (int i = 0; i < 4; i++) {
        __nv_bfloat16 hb = __float2bfloat16(f[i]);
        float r = f[i] - __bfloat162float(hb);
        __nv_bfloat16 lb = __float2bfloat16(r);
        h[i] = (unsigned)__bfloat16_as_ushort(hb);
        l[i] = (unsigned)__bfloat16_as_ushort(lb);
    }
    unsigned hA = h[0] | (h[1] << 16), hB = h[2] | (h[3] << 16);
    unsigned lA = l[0] | (l[1] << 16), lB = l[2] | (l[3] << 16);
    asm volatile("st.shared.v2.b32 [%0], {%1,%2};" :: "r"(hi_addr), "r"(hA), "r"(hB) : "memory");
    asm volatile("st.shared.v2.b32 [%0], {%1,%2};" :: "r"(lo_addr), "r"(lA), "r"(lB) : "memory");
}

// ---------------- K0: reset scratch ------------------------------------------
__global__ void k_init() {
    int i = blockIdx.x * blockDim.x + threadIdx.x;
    int stride = gridDim.x * blockDim.x;
    for (int j = i; j < B * VIN; j += stride) g_inpdist[j] = 0.0f;
    for (int j = i; j < VOUT; j += stride)    g_winner[j]  = -1;
    if (i < B) { g_rowmax[i] = 0u; g_cancopy[i] = 0; }
}

// ---------------- K1: attention softmax + scatter-add ------------------------
__global__ __launch_bounds__(256) void k_attn(const float* __restrict__ attn,
                                              const int*   __restrict__ inptok,
                                              float*       __restrict__ out_attn) {
    int b = blockIdx.x;
    __shared__ float red[256];
    const float* row = attn + b * S;

    float mx = -INFINITY;
    for (int s = threadIdx.x; s < S; s += 256) mx = fmaxf(mx, row[s]);
    red[threadIdx.x] = mx; __syncthreads();
    for (int off = 128; off > 0; off >>= 1) {
        if (threadIdx.x < off) red[threadIdx.x] = fmaxf(red[threadIdx.x], red[threadIdx.x + off]);
        __syncthreads();
    }
    mx = red[0]; __syncthreads();

    float sum = 0.0f;
    for (int s = threadIdx.x; s < S; s += 256) sum += expf(row[s] - mx);
    red[threadIdx.x] = sum; __syncthreads();
    for (int off = 128; off > 0; off >>= 1) {
        if (threadIdx.x < off) red[threadIdx.x] += red[threadIdx.x + off];
        __syncthreads();
    }
    sum = red[0];
    float inv = 1.0f / sum;

    for (int s = threadIdx.x; s < S; s += 256) {
        float p = expf(row[s] - mx) * inv;
        out_attn[b * S + s] = p;
        atomicAdd(&g_inpdist[b * VIN + inptok[b * S + s]], p);
    }
}

// ---------------- K2: winner index -------------------------------------------
__global__ void k_winner(const int* __restrict__ inp_to_act) {
    int j = blockIdx.x * blockDim.x + threadIdx.x;
    if (j < VIN) atomicMax(&g_winner[inp_to_act[j]], j);
}

// ---------------- K3: mma.sync GEMM logits = x @ W^T + b + log(mask) ---------
__global__ __launch_bounds__(256, 1) void k_gemm(const float* __restrict__ x,
                                                 const float* __restrict__ W,
                                                 const float* __restrict__ bias,
                                                 const float* __restrict__ mask,
                                                 float*       __restrict__ out_logits) {
    extern __shared__ char smem[];
    uint32_t sb = smem_u32(smem);
    int t = threadIdx.x;
    int lane = t & 31;
    int wid = t >> 5;
    int n0 = blockIdx.x * NTILE;
    int wm = (wid >> 2) * 64;   // warp M offset: 0 or 64
    int wn = (wid & 3) * 32;    // warp N offset: 0,32,64,96

    float acc[4][4][4];
#pragma unroll
    for (int mi = 0; mi < 4; mi++)
#pragma unroll
        for (int ni = 0; ni < 4; ni++)
#pragma unroll
            for (int r = 0; r < 4; r++) acc[mi][ni][r] = 0.0f;

    // prefetch W chunk 0
    float4 pw[4];
#pragma unroll
    for (int i = 0; i < 4; i++) {
        int g = t + i * 256;
        int row = g >> 3, k4 = (g & 7) << 2;
        int nb = n0 + row;
        pw[i] = (nb < VOUT) ? *(const float4*)(W + (size_t)nb * H + k4)
                            : make_float4(0.f, 0.f, 0.f, 0.f);
    }

    for (int c = 0; c < NCH; c++) {
        uint32_t buf = sb + (c & 1) * BUF_B;
        int k0 = c * KC;
        // convert + store current chunk (W from prefetch regs, x fresh: L2-hot)
#pragma unroll
        for (int i = 0; i < 4; i++) {
            int g = t + i * 256;
            int row = g >> 3, k4 = (g & 7) << 2;
            float4 xv = *(const float4*)(x + row * H + k0 + k4);
            uint32_t so = row * ROWB + k4 * 2;
            cvtstore(buf + XH_OFF + so, buf + XL_OFF + so, xv);
            cvtstore(buf + WH_OFF + so, buf + WL_OFF + so, pw[i]);
        }
        // prefetch next W chunk (overlaps the MMA below)
        if (c + 1 < NCH) {
#pragma unroll
            for (int i = 0; i < 4; i++) {
                int g = t + i * 256;
                int row = g >> 3, k4 = (g & 7) << 2;
                int nb = n0 + row;
                pw[i] = (nb < VOUT) ? *(const float4*)(W + (size_t)nb * H + (k0 + KC) + k4)
                                    : make_float4(0.f, 0.f, 0.f, 0.f);
            }
        }
        __syncthreads();

#pragma unroll
        for (int k16e = 0; k16e < 2; k16e++) {
            int k16 = k16e * 16;
            uint32_t bfh[4][2], bfl[4][2];
            {
                uint32_t q0, q1, q2, q3;
                ldm4(ldm_addr(buf + WH_OFF, wn,      k16, lane), q0, q1, q2, q3);
                bfh[0][0] = q0; bfh[1][0] = q1; bfh[0][1] = q2; bfh[1][1] = q3;
                ldm4(ldm_addr(buf + WH_OFF, wn + 16, k16, lane), q0, q1, q2, q3);
                bfh[2][0] = q0; bfh[3][0] = q1; bfh[2][1] = q2; bfh[3][1] = q3;
                ldm4(ldm_addr(buf + WL_OFF, wn,      k16, lane), q0, q1, q2, q3);
                bfl[0][0] = q0; bfl[1][0] = q1; bfl[0][1] = q2; bfl[1][1] = q3;
                ldm4(ldm_addr(buf + WL_OFF, wn + 16, k16, lane), q0, q1, q2, q3);
                bfl[2][0] = q0; bfl[3][0] = q1; bfl[2][1] = q2; bfl[3][1] = q3;
            }
#pragma unroll
            for (int mi = 0; mi < 4; mi++) {
                uint32_t ah[4], al[4];
                ldm4(ldm_addr(buf + XH_OFF, wm + mi * 16, k16, lane),
                     ah[0], ah[1], ah[2], ah[3]);
                ldm4(ldm_addr(buf + XL_OFF, wm + mi * 16, k16, lane),
                     al[0], al[1], al[2], al[3]);
#pragma unroll
                for (int ni = 0; ni < 4; ni++) {
                    mma_bf16(acc[mi][ni], ah, bfh[ni][0], bfh[ni][1]);
                    mma_bf16(acc[mi][ni], ah, bfl[ni][0], bfl[ni][1]);
                    mma_bf16(acc[mi][ni], al, bfh[ni][0], bfh[ni][1]);
                }
            }
        }
        __syncthreads();
    }

    // ---- epilogue ----
    uint32_t* srmax = (uint32_t*)(smem + RED_OFF);
    int*      scan  = (int*)(smem + CAN_OFF);
    if (t < 128) { srmax[t] = 0u; scan[t] = 0; }
    __syncthreads();

#pragma unroll
    for (int mi = 0; mi < 4; mi++) {
#pragma unroll
        for (int half = 0; half < 2; half++) {
            int m = wm + mi * 16 + (lane >> 2) + half * 8;
            float rmax = -INFINITY;
            int can = 0;
#pragma unroll
            for (int ni = 0; ni < 4; ni++) {
                int n = n0 + wn + ni * 8 + ((lane & 3) << 1);
                if (n < VOUT) {   // n even, VOUT even => n+1 < VOUT too
                    size_t idx = (size_t)m * VOUT + n;
                    float2 om = *(const float2*)(mask + idx);
                    float2 bv = *(const float2*)(bias + n);
                    float l0 = acc[mi][ni][half * 2 + 0] + bv.x + __logf(om.x);
                    float l1 = acc[mi][ni][half * 2 + 1] + bv.y + __logf(om.y);
                    *(float2*)(out_logits + idx) = make_float2(l0, l1);
                    rmax = fmaxf(rmax, fmaxf(l0, l1));
                    if (om.x > 0.0f && n != 0 && g_winner[n] >= 0) can = 1;
                    if (om.y > 0.0f && g_winner[n + 1] >= 0) can = 1;
                }
            }
            rmax = fmaxf(rmax, __shfl_xor_sync(0xFFFFFFFFu, rmax, 1));
            rmax = fmaxf(rmax, __shfl_xor_sync(0xFFFFFFFFu, rmax, 2));
            can |= __shfl_xor_sync(0xFFFFFFFFu, can, 1);
            can |= __shfl_xor_sync(0xFFFFFFFFu, can, 2);
            if ((lane & 3) == 0) {
                atomicMax(&srmax[m], f2ord(rmax));
                if (can) scan[m] = 1;
            }
        }
    }
    __syncthreads();
    if (t < 128) {
        atomicMax(&g_rowmax[t], srmax[t]);
        if (scan[t]) g_cancopy[t] = 1;
    }
}

// ---------------- K4: copy-or-generate gate ----------------------------------
__global__ void k_pog(const float* __restrict__ x,
                      const float* __restrict__ cogW,
                      const float* __restrict__ cogb,
                      float*       __restrict__ out_pog) {
    int b = blockIdx.x;
    int lane = threadIdx.x;
    float s0 = 0.f, s1 = 0.f;
    for (int k = lane; k < H; k += 32) {
        float xv = x[b * H + k];
        s0 += xv * cogW[k];
        s1 += xv * cogW[H + k];
    }
#pragma unroll
    for (int off = 16; off > 0; off >>= 1) {
        s0 += __shfl_xor_sync(0xFFFFFFFFu, s0, off);
        s1 += __shfl_xor_sync(0xFFFFFFFFu, s1, off);
    }
    if (lane == 0) {
        float l0 = s0 + cogb[0], l1 = s1 + cogb[1];
        int can = g_cancopy[b];
        float mx = can ? fmaxf(l0, l1) : l0;
        float e0 = expf(l0 - mx);
        float e1 = can ? expf(l1 - mx) : 0.0f;
        float inv = 1.0f / (e0 + e1);
        out_pog[2 * b]     = e0 * inv;
        out_pog[2 * b + 1] = e1 * inv;
    }
}

// ---------------- K5: row softmax over V_OUT + combine + log ------------------
__global__ __launch_bounds__(256) void k_final(float* __restrict__ logits_gen,
                                               float* __restrict__ out_probs,
                                               const float* __restrict__ pog) {
    int b = blockIdx.x;
    float mx = ord2f(g_rowmax[b]);
    __shared__ float red[256];
    const float* lrow = logits_gen + (size_t)b * VOUT;

    float sum = 0.0f;
    for (int n = threadIdx.x; n < VOUT; n += 256) sum += expf(lrow[n] - mx);
    red[threadIdx.x] = sum; __syncthreads();
    for (int off = 128; off > 0; off >>= 1) {
        if (threadIdx.x < off) red[threadIdx.x] += red[threadIdx.x + off];
        __syncthreads();
    }
    sum = red[0];
    float inv = 1.0f / sum;
    float pg = pog[2 * b], pc = pog[2 * b + 1];

    for (int n = threadIdx.x; n < VOUT; n += 256) {
        float p = expf(lrow[n] - mx) * inv;
        int w = g_winner[n];
        float ptr = (w >= 0) ? g_inpdist[(size_t)b * VIN + w] : 0.0f;
        out_probs[(size_t)b * VOUT + n] = logf(pg * p + pc * ptr);
        logits_gen[(size_t)b * VOUT + n] = p;
    }
}

// ---------------- launch ------------------------------------------------------
extern "C" void kernel_launch(void* const* d_in, const int* in_sizes, int n_in,
                              void* d_out, int out_size) {
    const float* x          = (const float*)d_in[0];
    const int*   inptensor  = (const int*)  d_in[1];
    const float* attn       = (const float*)d_in[2];
    const float* out_mask   = (const float*)d_in[3];
    const float* gen_W      = (const float*)d_in[4];
    const float* gen_b      = (const float*)d_in[5];
    const float* cog_W      = (const float*)d_in[6];
    const float* cog_b      = (const float*)d_in[7];
    const int*   inp_to_act = (const int*)  d_in[8];

    float* out = (float*)d_out;
    float* o_outprobs = out;
    float* o_pog      = out + (size_t)B * VOUT;
    float* o_gen      = o_pog + 2 * B;
    float* o_attn     = o_gen + (size_t)B * VOUT;

    cudaFuncSetAttribute(k_gemm, cudaFuncAttributeMaxDynamicSharedMemorySize, SMEM_TOTAL);

    k_init<<<1024, 256>>>();
    k_winner<<<(VIN + 255) / 256, 256>>>(inp_to_act);
    k_attn<<<B, 256>>>(attn, inptensor, o_attn);
    k_gemm<<<(VOUT + NTILE - 1) / NTILE, 256, SMEM_TOTAL>>>(x, gen_W, gen_b, out_mask, o_gen);
    k_pog<<<B, 32>>>(x, cog_W, cog_b, o_pog);
    k_final<<<B, 256>>>(o_gen, o_outprobs, o_pog);
}

// round 6
// speedup vs baseline: 1.9856x; 1.1659x over previous
#include <cuda_runtime.h>
#include <cuda_bf16.h>
#include <stdint.h>
#include <math.h>

#define B    128
#define H    1024
#define S    512
#define VOUT 50000
#define VIN  32000

#define NTILE  128
#define KC     32
#define NCH    (H / KC)            // 32 chunks per tile
#define NT     ((VOUT + NTILE - 1) / NTILE)   // 391 tiles
#define GRID   148

#define NTHREADS 384               // warps 0-7 consumers, 8-11 producers

// smem: stage = 4 tiles (XH, XL, WH, WL), each 128 rows x 80B
#define ROWB    80
#define TILE_B  (128 * ROWB)       // 10240
#define XH      0
#define XL      (1 * TILE_B)
#define WH      (2 * TILE_B)
#define WL      (3 * TILE_B)
#define STAGE_B (4 * TILE_B)       // 40960
#define NSTAGE  4
#define TILES_OFF 1024
#define RED_OFF  (TILES_OFF + NSTAGE * STAGE_B)   // 164864
#define CAN_OFF  (RED_OFF + 512)
#define SMEM_TOTAL (CAN_OFF + 512)                // 165888

// ---------------- persistent device scratch ----------------------------------
__device__ float          g_inpdist[B * VIN];
__device__ int            g_winner[VOUT];
__device__ unsigned int   g_rowmax[B];
__device__ int            g_cancopy[B];
__device__ __nv_bfloat16  g_xh[B * H];
__device__ __nv_bfloat16  g_xl[B * H];

__device__ __forceinline__ unsigned int f2ord(float f) {
    unsigned int u = __float_as_uint(f);
    return (u & 0x80000000u) ? ~u : (u | 0x80000000u);
}
__device__ __forceinline__ float ord2f(unsigned int e) {
    unsigned int u = (e & 0x80000000u) ? (e & 0x7FFFFFFFu) : ~e;
    return __uint_as_float(u);
}

__device__ __forceinline__ uint32_t smem_u32(const void* p) {
    uint32_t a;
    asm("{ .reg .u64 t; cvta.to.shared.u64 t, %1; cvt.u32.u64 %0, t; }" : "=r"(a) : "l"(p));
    return a;
}

#define MBARRIER_INIT(addr, cnt) \
    asm volatile("mbarrier.init.shared.b64 [%0], %1;" :: "r"(addr), "r"(cnt) : "memory")
#define MBARRIER_ARRIVE(addr) \
    asm volatile("mbarrier.arrive.shared.b64 _, [%0];" :: "r"(addr) : "memory")
#define MBARRIER_WAIT_PARITY(mbar_addr, phase) do {                                  \
    uint32_t _mb = (uint32_t)(mbar_addr);                                            \
    uint32_t _ph = (uint32_t)(phase);                                                \
    asm volatile(                                                                    \
        "{\n\t.reg .pred P1;\n\t"                                                    \
        "WAIT_LOOP_%=:\n\t"                                                          \
        "mbarrier.try_wait.parity.acquire.cta.shared::cta.b64 P1, [%0], %1, 0x989680;\n\t" \
        "@P1 bra.uni WAIT_DONE_%=;\n\t"                                              \
        "bra.uni WAIT_LOOP_%=;\n\t"                                                  \
        "WAIT_DONE_%=:\n\t}"                                                         \
        :: "r"(_mb), "r"(_ph) : "memory");                                           \
} while (0)

__device__ __forceinline__ void ldm4(uint32_t addr, uint32_t& r0, uint32_t& r1,
                                     uint32_t& r2, uint32_t& r3) {
    asm volatile("ldmatrix.sync.aligned.m8n8.x4.shared.b16 {%0,%1,%2,%3}, [%4];"
                 : "=r"(r0), "=r"(r1), "=r"(r2), "=r"(r3) : "r"(addr));
}
__device__ __forceinline__ uint32_t ldm_addr(uint32_t tile, int base_row, int k16, int lane) {
    int mat = lane >> 3;
    int row = base_row + (lane & 7) + ((mat & 1) << 3);
    int ke  = k16 + ((mat >> 1) << 3);
    return tile + row * ROWB + ke * 2;
}
__device__ __forceinline__ void mma_bf16(float* c, const uint32_t* a, uint32_t b0, uint32_t b1) {
    asm volatile(
        "mma.sync.aligned.m16n8k16.row.col.f32.bf16.bf16.f32 "
        "{%0,%1,%2,%3}, {%4,%5,%6,%7}, {%8,%9}, {%0,%1,%2,%3};"
        : "+f"(c[0]), "+f"(c[1]), "+f"(c[2]), "+f"(c[3])
        : "r"(a[0]), "r"(a[1]), "r"(a[2]), "r"(a[3]), "r"(b0), "r"(b1));
}
__device__ __forceinline__ void cvtstore(uint32_t hi_addr, uint32_t lo_addr, float4 v) {
    float f[4] = {v.x, v.y, v.z, v.w};
    unsigned h[4], l[4];
#pragma unroll
    for (int i = 0; i < 4; i++) {
        __nv_bfloat16 hb = __float2bfloat16(f[i]);
        float r = f[i] - __bfloat162float(hb);
        __nv_bfloat16 lb = __float2bfloat16(r);
        h[i] = (unsigned)__bfloat16_as_ushort(hb);
        l[i] = (unsigned)__bfloat16_as_ushort(lb);
    }
    unsigned hA = h[0] | (h[1] << 16), hB = h[2] | (h[3] << 16);
    unsigned lA = l[0] | (l[1] << 16), lB = l[2] | (l[3] << 16);
    asm volatile("st.shared.v2.b32 [%0], {%1,%2};" :: "r"(hi_addr), "r"(hA), "r"(hB) : "memory");
    asm volatile("st.shared.v2.b32 [%0], {%1,%2};" :: "r"(lo_addr), "r"(lA), "r"(lB) : "memory");
}

// ---------------- K0: reset scratch ------------------------------------------
__global__ void k_init() {
    int i = blockIdx.x * blockDim.x + threadIdx.x;
    int stride = gridDim.x * blockDim.x;
    for (int j = i; j < B * VIN; j += stride) g_inpdist[j] = 0.0f;
    for (int j = i; j < VOUT; j += stride)    g_winner[j]  = -1;
    if (i < B) { g_rowmax[i] = 0u; g_cancopy[i] = 0; }
}

// ---------------- K0b: convert x -> bf16 hi/lo (once) ------------------------
__global__ void k_xcvt(const float* __restrict__ x) {
    int i = blockIdx.x * blockDim.x + threadIdx.x;   // per 4 floats
    if (i < B * H / 4) {
        float4 v = ((const float4*)x)[i];
        float f[4] = {v.x, v.y, v.z, v.w};
        unsigned h[4], l[4];
#pragma unroll
        for (int j = 0; j < 4; j++) {
            __nv_bfloat16 hb = __float2bfloat16(f[j]);
            float r = f[j] - __bfloat162float(hb);
            __nv_bfloat16 lb = __float2bfloat16(r);
            h[j] = (unsigned)__bfloat16_as_ushort(hb);
            l[j] = (unsigned)__bfloat16_as_ushort(lb);
        }
        ((uint2*)g_xh)[i] = make_uint2(h[0] | (h[1] << 16), h[2] | (h[3] << 16));
        ((uint2*)g_xl)[i] = make_uint2(l[0] | (l[1] << 16), l[2] | (l[3] << 16));
    }
}

// ---------------- K1: attention softmax + scatter-add ------------------------
__global__ __launch_bounds__(256) void k_attn(const float* __restrict__ attn,
                                              const int*   __restrict__ inptok,
                                              float*       __restrict__ out_attn) {
    int b = blockIdx.x;
    __shared__ float red[256];
    const float* row = attn + b * S;

    float mx = -INFINITY;
    for (int s = threadIdx.x; s < S; s += 256) mx = fmaxf(mx, row[s]);
    red[threadIdx.x] = mx; __syncthreads();
    for (int off = 128; off > 0; off >>= 1) {
        if (threadIdx.x < off) red[threadIdx.x] = fmaxf(red[threadIdx.x], red[threadIdx.x + off]);
        __syncthreads();
    }
    mx = red[0]; __syncthreads();

    float sum = 0.0f;
    for (int s = threadIdx.x; s < S; s += 256) sum += expf(row[s] - mx);
    red[threadIdx.x] = sum; __syncthreads();
    for (int off = 128; off > 0; off >>= 1) {
        if (threadIdx.x < off) red[threadIdx.x] += red[threadIdx.x + off];
        __syncthreads();
    }
    sum = red[0];
    float inv = 1.0f / sum;

    for (int s = threadIdx.x; s < S; s += 256) {
        float p = expf(row[s] - mx) * inv;
        out_attn[b * S + s] = p;
        atomicAdd(&g_inpdist[b * VIN + inptok[b * S + s]], p);
    }
}

// ---------------- K2: winner index -------------------------------------------
__global__ void k_winner(const int* __restrict__ inp_to_act) {
    int j = blockIdx.x * blockDim.x + threadIdx.x;
    if (j < VIN) atomicMax(&g_winner[inp_to_act[j]], j);
}

// ---------------- K3: warp-specialized persistent GEMM ------------------------
__global__ __launch_bounds__(NTHREADS, 1) void k_gemm(const float* __restrict__ W,
                                                      const float* __restrict__ bias,
                                                      const float* __restrict__ mask,
                                                      float*       __restrict__ out_logits) {
    extern __shared__ char smem[];
    uint32_t sb = smem_u32(smem);
    int t = threadIdx.x;
    int lane = t & 31;
    int wid = t >> 5;
    uint32_t* srmax = (uint32_t*)(smem + RED_OFF);
    int*      scan  = (int*)(smem + CAN_OFF);

    if (t == 0) {
#pragma unroll
        for (int s = 0; s < NSTAGE; s++) {
            MBARRIER_INIT(sb + s * 16,     128);   // full[s]: 128 producer threads
            MBARRIER_INIT(sb + s * 16 + 8, 256);   // empty[s]: 256 consumer threads
        }
    }
    if (t < 128) { srmax[t] = 0u; scan[t] = 0; }
    __syncthreads();

    if (t >= 256) {
        // ================= producers (warps 8-11) =================
        int pt = t - 256;
        int sc = 0, ph = 1;
        for (int tile = blockIdx.x; tile < NT; tile += GRID) {
            int n0 = tile * NTILE;
            for (int c = 0; c < NCH; c++) {
                MBARRIER_WAIT_PARITY(sb + sc * 16 + 8, ph);
                uint32_t buf = sb + TILES_OFF + sc * STAGE_B;
                int k0 = c * KC;
                // x tiles: thread pt copies row pt (bf16, preconverted)
                {
                    const uint4* xh4 = (const uint4*)(g_xh + pt * H + k0);
                    const uint4* xl4 = (const uint4*)(g_xl + pt * H + k0);
                    uint32_t ro = buf + pt * ROWB;
#pragma unroll
                    for (int j = 0; j < 4; j++) {
                        uint4 v = xh4[j];
                        asm volatile("st.shared.v4.b32 [%0], {%1,%2,%3,%4};"
                                     :: "r"(ro + XH + j * 16),
                                        "r"(v.x), "r"(v.y), "r"(v.z), "r"(v.w) : "memory");
                        uint4 w = xl4[j];
                        asm volatile("st.shared.v4.b32 [%0], {%1,%2,%3,%4};"
                                     :: "r"(ro + XL + j * 16),
                                        "r"(w.x), "r"(w.y), "r"(w.z), "r"(w.w) : "memory");
                    }
                }
                // W tile: convert fp32 -> bf16 hi/lo
#pragma unroll
                for (int i = 0; i < 8; i++) {
                    int g = pt + i * 128;
                    int row = g >> 3, k4 = (g & 7) << 2;
                    int nb = n0 + row;
                    float4 wv = (nb < VOUT)
                        ? *(const float4*)(W + (size_t)nb * H + k0 + k4)
                        : make_float4(0.f, 0.f, 0.f, 0.f);
                    uint32_t so = row * ROWB + k4 * 2;
                    cvtstore(buf + WH + so, buf + WL + so, wv);
                }
                MBARRIER_ARRIVE(sb + sc * 16);
                if (++sc == NSTAGE) { sc = 0; ph ^= 1; }
            }
        }
    } else {
        // ================= consumers (warps 0-7) =================
        int wm = (wid >> 2) * 64;
        int wn = (wid & 3) * 32;
        int sc = 0, ph = 0;

        for (int tile = blockIdx.x; tile < NT; tile += GRID) {
            int n0 = tile * NTILE;
            float acc[4][4][4];
#pragma unroll
            for (int mi = 0; mi < 4; mi++)
#pragma unroll
                for (int ni = 0; ni < 4; ni++)
#pragma unroll
                    for (int r = 0; r < 4; r++) acc[mi][ni][r] = 0.0f;

            for (int c = 0; c < NCH; c++) {
                MBARRIER_WAIT_PARITY(sb + sc * 16, ph);
                uint32_t buf = sb + TILES_OFF + sc * STAGE_B;
#pragma unroll
                for (int k16e = 0; k16e < 2; k16e++) {
                    int k16 = k16e * 16;
                    uint32_t bfh[4][2], bfl[4][2];
                    {
                        uint32_t q0, q1, q2, q3;
                        ldm4(ldm_addr(buf + WH, wn,      k16, lane), q0, q1, q2, q3);
                        bfh[0][0] = q0; bfh[1][0] = q1; bfh[0][1] = q2; bfh[1][1] = q3;
                        ldm4(ldm_addr(buf + WH, wn + 16, k16, lane), q0, q1, q2, q3);
                        bfh[2][0] = q0; bfh[3][0] = q1; bfh[2][1] = q2; bfh[3][1] = q3;
                        ldm4(ldm_addr(buf + WL, wn,      k16, lane), q0, q1, q2, q3);
                        bfl[0][0] = q0; bfl[1][0] = q1; bfl[0][1] = q2; bfl[1][1] = q3;
                        ldm4(ldm_addr(buf + WL, wn + 16, k16, lane), q0, q1, q2, q3);
                        bfl[2][0] = q0; bfl[3][0] = q1; bfl[2][1] = q2; bfl[3][1] = q3;
                    }
#pragma unroll
                    for (int mi = 0; mi < 4; mi++) {
                        uint32_t ah[4], al[4];
                        ldm4(ldm_addr(buf + XH, wm + mi * 16, k16, lane),
                             ah[0], ah[1], ah[2], ah[3]);
                        ldm4(ldm_addr(buf + XL, wm + mi * 16, k16, lane),
                             al[0], al[1], al[2], al[3]);
#pragma unroll
                        for (int ni = 0; ni < 4; ni++) {
                            mma_bf16(acc[mi][ni], ah, bfh[ni][0], bfh[ni][1]);
                            mma_bf16(acc[mi][ni], ah, bfl[ni][0], bfl[ni][1]);
                            mma_bf16(acc[mi][ni], al, bfh[ni][0], bfh[ni][1]);
                        }
                    }
                }
                MBARRIER_ARRIVE(sb + sc * 16 + 8);
                if (++sc == NSTAGE) { sc = 0; ph ^= 1; }
            }

            // ---- per-tile epilogue (consumers only) ----
#pragma unroll
            for (int mi = 0; mi < 4; mi++) {
#pragma unroll
                for (int half = 0; half < 2; half++) {
                    int m = wm + mi * 16 + (lane >> 2) + half * 8;
                    float rmax = -INFINITY;
                    int can = 0;
#pragma unroll
                    for (int ni = 0; ni < 4; ni++) {
                        int n = n0 + wn + ni * 8 + ((lane & 3) << 1);
                        if (n < VOUT) {
                            size_t idx = (size_t)m * VOUT + n;
                            float2 om = *(const float2*)(mask + idx);
                            float2 bv = *(const float2*)(bias + n);
                            float l0 = acc[mi][ni][half * 2 + 0] + bv.x + __logf(om.x);
                            float l1 = acc[mi][ni][half * 2 + 1] + bv.y + __logf(om.y);
                            *(float2*)(out_logits + idx) = make_float2(l0, l1);
                            rmax = fmaxf(rmax, fmaxf(l0, l1));
                            if (om.x > 0.0f && n != 0 && g_winner[n] >= 0) can = 1;
                            if (om.y > 0.0f && g_winner[n + 1] >= 0) can = 1;
                        }
                    }
                    rmax = fmaxf(rmax, __shfl_xor_sync(0xFFFFFFFFu, rmax, 1));
                    rmax = fmaxf(rmax, __shfl_xor_sync(0xFFFFFFFFu, rmax, 2));
                    can |= __shfl_xor_sync(0xFFFFFFFFu, can, 1);
                    can |= __shfl_xor_sync(0xFFFFFFFFu, can, 2);
                    if ((lane & 3) == 0) {
                        atomicMax(&srmax[m], f2ord(rmax));
                        if (can) scan[m] = 1;
                    }
                }
            }
            asm volatile("bar.sync 1, 256;" ::: "memory");
            if (t < 128) {
                atomicMax(&g_rowmax[t], srmax[t]);
                if (scan[t]) g_cancopy[t] = 1;
                srmax[t] = 0u;
                scan[t] = 0;
            }
            asm volatile("bar.sync 1, 256;" ::: "memory");
        }
    }
}

// ---------------- K4: copy-or-generate gate ----------------------------------
__global__ void k_pog(const float* __restrict__ x,
                      const float* __restrict__ cogW,
                      const float* __restrict__ cogb,
                      float*       __restrict__ out_pog) {
    int b = blockIdx.x;
    int lane = threadIdx.x;
    float s0 = 0.f, s1 = 0.f;
    for (int k = lane; k < H; k += 32) {
        float xv = x[b * H + k];
        s0 += xv * cogW[k];
        s1 += xv * cogW[H + k];
    }
#pragma unroll
    for (int off = 16; off > 0; off >>= 1) {
        s0 += __shfl_xor_sync(0xFFFFFFFFu, s0, off);
        s1 += __shfl_xor_sync(0xFFFFFFFFu, s1, off);
    }
    if (lane == 0) {
        float l0 = s0 + cogb[0], l1 = s1 + cogb[1];
        int can = g_cancopy[b];
        float mx = can ? fmaxf(l0, l1) : l0;
        float e0 = expf(l0 - mx);
        float e1 = can ? expf(l1 - mx) : 0.0f;
        float inv = 1.0f / (e0 + e1);
        out_pog[2 * b]     = e0 * inv;
        out_pog[2 * b + 1] = e1 * inv;
    }
}

// ---------------- K5: row softmax over V_OUT + combine + log ------------------
__global__ __launch_bounds__(256) void k_final(float* __restrict__ logits_gen,
                                               float* __restrict__ out_probs,
                                               const float* __restrict__ pog) {
    int b = blockIdx.x;
    float mx = ord2f(g_rowmax[b]);
    __shared__ float red[256];
    const float* lrow = logits_gen + (size_t)b * VOUT;

    float sum = 0.0f;
    for (int n = threadIdx.x; n < VOUT; n += 256) sum += expf(lrow[n] - mx);
    red[threadIdx.x] = sum; __syncthreads();
    for (int off = 128; off > 0; off >>= 1) {
        if (threadIdx.x < off) red[threadIdx.x] += red[threadIdx.x + off];
        __syncthreads();
    }
    sum = red[0];
    float inv = 1.0f / sum;
    float pg = pog[2 * b], pc = pog[2 * b + 1];

    for (int n = threadIdx.x; n < VOUT; n += 256) {
        float p = expf(lrow[n] - mx) * inv;
        int w = g_winner[n];
        float ptr = (w >= 0) ? g_inpdist[(size_t)b * VIN + w] : 0.0f;
        out_probs[(size_t)b * VOUT + n] = logf(pg * p + pc * ptr);
        logits_gen[(size_t)b * VOUT + n] = p;
    }
}

// ---------------- launch ------------------------------------------------------
extern "C" void kernel_launch(void* const* d_in, const int* in_sizes, int n_in,
                              void* d_out, int out_size) {
    const float* x          = (const float*)d_in[0];
    const int*   inptensor  = (const int*)  d_in[1];
    const float* attn       = (const float*)d_in[2];
    const float* out_mask   = (const float*)d_in[3];
    const float* gen_W      = (const float*)d_in[4];
    const float* gen_b      = (const float*)d_in[5];
    const float* cog_W      = (const float*)d_in[6];
    const float* cog_b      = (const float*)d_in[7];
    const int*   inp_to_act = (const int*)  d_in[8];

    float* out = (float*)d_out;
    float* o_outprobs = out;
    float* o_pog      = out + (size_t)B * VOUT;
    float* o_gen      = o_pog + 2 * B;
    float* o_attn     = o_gen + (size_t)B * VOUT;

    cudaFuncSetAttribute(k_gemm, cudaFuncAttributeMaxDynamicSharedMemorySize, SMEM_TOTAL);

    k_init<<<1024, 256>>>();
    k_xcvt<<<(B * H / 4 + 255) / 256, 256>>>(x);
    k_winner<<<(VIN + 255) / 256, 256>>>(inp_to_act);
    k_attn<<<B, 256>>>(attn, inptensor, o_attn);
    k_gemm<<<GRID, NTHREADS, SMEM_TOTAL>>>(gen_W, gen_b, out_mask, o_gen);
    k_pog<<<B, 32>>>(x, cog_W, cog_b, o_pog);
    k_final<<<B, 256>>>(o_gen, o_outprobs, o_pog);
}

// round 7
// speedup vs baseline: 2.1570x; 1.0863x over previous
#include <cuda_runtime.h>
#include <cuda_fp16.h>
#include <stdint.h>
#include <math.h>

#define B    128
#define H    1024
#define S    512
#define VOUT 50000
#define VIN  32000

#define NTILE  128
#define KC     32
#define NCH    (H / KC)            // 32 chunks per tile
#define NT     ((VOUT + NTILE - 1) / NTILE)   // 391 tiles
#define GRID   148

#define NTHREADS 384               // warps 0-7 consumers, 8-11 producers

// smem stage = 3 tiles (XH, XL, WH), each 128 rows x 80B
#define ROWB    80
#define TILE_B  (128 * ROWB)       // 10240
#define XH      0
#define XL      (1 * TILE_B)
#define WH      (2 * TILE_B)
#define STAGE_B (3 * TILE_B)       // 30720
#define NSTAGE  5
#define TILES_OFF 1024
#define RED_OFF  (TILES_OFF + NSTAGE * STAGE_B)   // 154624
#define CAN_OFF  (RED_OFF + 512)
#define SMEM_TOTAL (CAN_OFF + 512)                // 155648

// ---------------- persistent device scratch ----------------------------------
__device__ float        g_inpdist[B * VIN];
__device__ int          g_winner[VOUT];
__device__ unsigned int g_rowmax[B];
__device__ int          g_cancopy[B];
__device__ __half       g_xh[B * H];
__device__ __half       g_xl[B * H];

__device__ __forceinline__ unsigned int f2ord(float f) {
    unsigned int u = __float_as_uint(f);
    return (u & 0x80000000u) ? ~u : (u | 0x80000000u);
}
__device__ __forceinline__ float ord2f(unsigned int e) {
    unsigned int u = (e & 0x80000000u) ? (e & 0x7FFFFFFFu) : ~e;
    return __uint_as_float(u);
}

__device__ __forceinline__ uint32_t smem_u32(const void* p) {
    uint32_t a;
    asm("{ .reg .u64 t; cvta.to.shared.u64 t, %1; cvt.u32.u64 %0, t; }" : "=r"(a) : "l"(p));
    return a;
}

#define MBARRIER_INIT(addr, cnt) \
    asm volatile("mbarrier.init.shared.b64 [%0], %1;" :: "r"(addr), "r"(cnt) : "memory")
#define MBARRIER_ARRIVE(addr) \
    asm volatile("mbarrier.arrive.shared.b64 _, [%0];" :: "r"(addr) : "memory")
#define MBARRIER_WAIT_PARITY(mbar_addr, phase) do {                                  \
    uint32_t _mb = (uint32_t)(mbar_addr);                                            \
    uint32_t _ph = (uint32_t)(phase);                                                \
    asm volatile(                                                                    \
        "{\n\t.reg .pred P1;\n\t"                                                    \
        "WAIT_LOOP_%=:\n\t"                                                          \
        "mbarrier.try_wait.parity.acquire.cta.shared::cta.b64 P1, [%0], %1, 0x989680;\n\t" \
        "@P1 bra.uni WAIT_DONE_%=;\n\t"                                              \
        "bra.uni WAIT_LOOP_%=;\n\t"                                                  \
        "WAIT_DONE_%=:\n\t}"                                                         \
        :: "r"(_mb), "r"(_ph) : "memory");                                           \
} while (0)

__device__ __forceinline__ void ldm4(uint32_t addr, uint32_t& r0, uint32_t& r1,
                                     uint32_t& r2, uint32_t& r3) {
    asm volatile("ldmatrix.sync.aligned.m8n8.x4.shared.b16 {%0,%1,%2,%3}, [%4];"
                 : "=r"(r0), "=r"(r1), "=r"(r2), "=r"(r3) : "r"(addr));
}
__device__ __forceinline__ uint32_t ldm_addr(uint32_t tile, int base_row, int k16, int lane) {
    int mat = lane >> 3;
    int row = base_row + (lane & 7) + ((mat & 1) << 3);
    int ke  = k16 + ((mat >> 1) << 3);
    return tile + row * ROWB + ke * 2;
}
__device__ __forceinline__ void mma_f16(float* c, const uint32_t* a, uint32_t b0, uint32_t b1) {
    asm volatile(
        "mma.sync.aligned.m16n8k16.row.col.f32.f16.f16.f32 "
        "{%0,%1,%2,%3}, {%4,%5,%6,%7}, {%8,%9}, {%0,%1,%2,%3};"
        : "+f"(c[0]), "+f"(c[1]), "+f"(c[2]), "+f"(c[3])
        : "r"(a[0]), "r"(a[1]), "r"(a[2]), "r"(a[3]), "r"(b0), "r"(b1));
}

// ---------------- K0: reset scratch ------------------------------------------
__global__ void k_init() {
    int i = blockIdx.x * blockDim.x + threadIdx.x;
    int stride = gridDim.x * blockDim.x;
    for (int j = i; j < B * VIN; j += stride) g_inpdist[j] = 0.0f;
    for (int j = i; j < VOUT; j += stride)    g_winner[j]  = -1;
    if (i < B) { g_rowmax[i] = 0u; g_cancopy[i] = 0; }
}

// ---------------- K0b: convert x -> fp16 hi/lo (once) ------------------------
__global__ void k_xcvt(const float* __restrict__ x) {
    int i = blockIdx.x * blockDim.x + threadIdx.x;   // per 4 floats
    if (i < B * H / 4) {
        float4 v = ((const float4*)x)[i];
        float f[4] = {v.x, v.y, v.z, v.w};
        unsigned h[4], l[4];
#pragma unroll
        for (int j = 0; j < 4; j++) {
            __half hb = __float2half_rn(f[j]);
            float r = f[j] - __half2float(hb);
            __half lb = __float2half_rn(r);
            h[j] = (unsigned)__half_as_ushort(hb);
            l[j] = (unsigned)__half_as_ushort(lb);
        }
        ((uint2*)g_xh)[i] = make_uint2(h[0] | (h[1] << 16), h[2] | (h[3] << 16));
        ((uint2*)g_xl)[i] = make_uint2(l[0] | (l[1] << 16), l[2] | (l[3] << 16));
    }
}

// ---------------- K1: attention softmax + scatter-add ------------------------
__global__ __launch_bounds__(256) void k_attn(const float* __restrict__ attn,
                                              const int*   __restrict__ inptok,
                                              float*       __restrict__ out_attn) {
    int b = blockIdx.x;
    __shared__ float red[256];
    const float* row = attn + b * S;

    float mx = -INFINITY;
    for (int s = threadIdx.x; s < S; s += 256) mx = fmaxf(mx, row[s]);
    red[threadIdx.x] = mx; __syncthreads();
    for (int off = 128; off > 0; off >>= 1) {
        if (threadIdx.x < off) red[threadIdx.x] = fmaxf(red[threadIdx.x], red[threadIdx.x + off]);
        __syncthreads();
    }
    mx = red[0]; __syncthreads();

    float sum = 0.0f;
    for (int s = threadIdx.x; s < S; s += 256) sum += expf(row[s] - mx);
    red[threadIdx.x] = sum; __syncthreads();
    for (int off = 128; off > 0; off >>= 1) {
        if (threadIdx.x < off) red[threadIdx.x] += red[threadIdx.x + off];
        __syncthreads();
    }
    sum = red[0];
    float inv = 1.0f / sum;

    for (int s = threadIdx.x; s < S; s += 256) {
        float p = expf(row[s] - mx) * inv;
        out_attn[b * S + s] = p;
        atomicAdd(&g_inpdist[b * VIN + inptok[b * S + s]], p);
    }
}

// ---------------- K2: winner index -------------------------------------------
__global__ void k_winner(const int* __restrict__ inp_to_act) {
    int j = blockIdx.x * blockDim.x + threadIdx.x;
    if (j < VIN) atomicMax(&g_winner[inp_to_act[j]], j);
}

// ---------------- K3: warp-specialized persistent GEMM ------------------------
__global__ __launch_bounds__(NTHREADS, 1) void k_gemm(const float* __restrict__ W,
                                                      const float* __restrict__ bias,
                                                      const float* __restrict__ mask,
                                                      float*       __restrict__ out_logits) {
    extern __shared__ char smem[];
    uint32_t sb = smem_u32(smem);
    int t = threadIdx.x;
    int lane = t & 31;
    int wid = t >> 5;
    uint32_t* srmax = (uint32_t*)(smem + RED_OFF);
    int*      scan  = (int*)(smem + CAN_OFF);

    if (t == 0) {
#pragma unroll
        for (int s = 0; s < NSTAGE; s++) {
            MBARRIER_INIT(sb + s * 16,     128);   // full[s]: 128 producer threads
            MBARRIER_INIT(sb + s * 16 + 8, 256);   // empty[s]: 256 consumer threads
        }
    }
    if (t < 128) { srmax[t] = 0u; scan[t] = 0; }
    __syncthreads();

    if (t >= 256) {
        // ================= producers (warps 8-11) =================
        int pt = t - 256;
        int sc = 0, ph = 1;
        for (int tile = blockIdx.x; tile < NT; tile += GRID) {
            int n0 = tile * NTILE;
            for (int c = 0; c < NCH; c++) {
                MBARRIER_WAIT_PARITY(sb + sc * 16 + 8, ph);
                uint32_t buf = sb + TILES_OFF + sc * STAGE_B;
                int k0 = c * KC;
                // x tiles: thread pt copies row pt (fp16, preconverted)
                {
                    const uint4* xh4 = (const uint4*)(g_xh + pt * H + k0);
                    const uint4* xl4 = (const uint4*)(g_xl + pt * H + k0);
                    uint32_t ro = buf + pt * ROWB;
#pragma unroll
                    for (int j = 0; j < 4; j++) {
                        uint4 v = xh4[j];
                        asm volatile("st.shared.v4.b32 [%0], {%1,%2,%3,%4};"
                                     :: "r"(ro + XH + j * 16),
                                        "r"(v.x), "r"(v.y), "r"(v.z), "r"(v.w) : "memory");
                        uint4 w = xl4[j];
                        asm volatile("st.shared.v4.b32 [%0], {%1,%2,%3,%4};"
                                     :: "r"(ro + XL + j * 16),
                                        "r"(w.x), "r"(w.y), "r"(w.z), "r"(w.w) : "memory");
                    }
                }
                // W tile: convert fp32 -> fp16 hi only
#pragma unroll
                for (int i = 0; i < 8; i++) {
                    int g = pt + i * 128;
                    int row = g >> 3, k4 = (g & 7) << 2;
                    int nb = n0 + row;
                    float4 wv = (nb < VOUT)
                        ? *(const float4*)(W + (size_t)nb * H + k0 + k4)
                        : make_float4(0.f, 0.f, 0.f, 0.f);
                    unsigned h0 = (unsigned)__half_as_ushort(__float2half_rn(wv.x));
                    unsigned h1 = (unsigned)__half_as_ushort(__float2half_rn(wv.y));
                    unsigned h2 = (unsigned)__half_as_ushort(__float2half_rn(wv.z));
                    unsigned h3 = (unsigned)__half_as_ushort(__float2half_rn(wv.w));
                    unsigned a = h0 | (h1 << 16), b = h2 | (h3 << 16);
                    asm volatile("st.shared.v2.b32 [%0], {%1,%2};"
                                 :: "r"(buf + WH + row * ROWB + k4 * 2),
                                    "r"(a), "r"(b) : "memory");
                }
                MBARRIER_ARRIVE(sb + sc * 16);
                if (++sc == NSTAGE) { sc = 0; ph ^= 1; }
            }
        }
    } else {
        // ================= consumers (warps 0-7) =================
        int wm = (wid >> 2) * 64;
        int wn = (wid & 3) * 32;
        int sc = 0, ph = 0;

        for (int tile = blockIdx.x; tile < NT; tile += GRID) {
            int n0 = tile * NTILE;
            float acc[4][4][4];
#pragma unroll
            for (int mi = 0; mi < 4; mi++)
#pragma unroll
                for (int ni = 0; ni < 4; ni++)
#pragma unroll
                    for (int r = 0; r < 4; r++) acc[mi][ni][r] = 0.0f;

            for (int c = 0; c < NCH; c++) {
                MBARRIER_WAIT_PARITY(sb + sc * 16, ph);
                uint32_t buf = sb + TILES_OFF + sc * STAGE_B;
#pragma unroll
                for (int k16e = 0; k16e < 2; k16e++) {
                    int k16 = k16e * 16;
                    uint32_t bh[4][2];
                    {
                        uint32_t q0, q1, q2, q3;
                        ldm4(ldm_addr(buf + WH, wn,      k16, lane), q0, q1, q2, q3);
                        bh[0][0] = q0; bh[1][0] = q1; bh[0][1] = q2; bh[1][1] = q3;
                        ldm4(ldm_addr(buf + WH, wn + 16, k16, lane), q0, q1, q2, q3);
                        bh[2][0] = q0; bh[3][0] = q1; bh[2][1] = q2; bh[3][1] = q3;
                    }
                    // process mi in pairs: 8 independent MMAs between acc reuses
#pragma unroll
                    for (int mp = 0; mp < 2; mp++) {
                        uint32_t ah[2][4], al[2][4];
                        ldm4(ldm_addr(buf + XH, wm + (mp * 2 + 0) * 16, k16, lane),
                             ah[0][0], ah[0][1], ah[0][2], ah[0][3]);
                        ldm4(ldm_addr(buf + XH, wm + (mp * 2 + 1) * 16, k16, lane),
                             ah[1][0], ah[1][1], ah[1][2], ah[1][3]);
                        ldm4(ldm_addr(buf + XL, wm + (mp * 2 + 0) * 16, k16, lane),
                             al[0][0], al[0][1], al[0][2], al[0][3]);
                        ldm4(ldm_addr(buf + XL, wm + (mp * 2 + 1) * 16, k16, lane),
                             al[1][0], al[1][1], al[1][2], al[1][3]);
#pragma unroll
                        for (int q = 0; q < 2; q++)
#pragma unroll
                            for (int ni = 0; ni < 4; ni++)
                                mma_f16(acc[mp * 2 + q][ni], ah[q], bh[ni][0], bh[ni][1]);
#pragma unroll
                        for (int q = 0; q < 2; q++)
#pragma unroll
                            for (int ni = 0; ni < 4; ni++)
                                mma_f16(acc[mp * 2 + q][ni], al[q], bh[ni][0], bh[ni][1]);
                    }
                }
                MBARRIER_ARRIVE(sb + sc * 16 + 8);
                if (++sc == NSTAGE) { sc = 0; ph ^= 1; }
            }

            // ---- per-tile epilogue (consumers only) ----
#pragma unroll
            for (int mi = 0; mi < 4; mi++) {
#pragma unroll
                for (int half = 0; half < 2; half++) {
                    int m = wm + mi * 16 + (lane >> 2) + half * 8;
                    float rmax = -INFINITY;
                    int can = 0;
#pragma unroll
                    for (int ni = 0; ni < 4; ni++) {
                        int n = n0 + wn + ni * 8 + ((lane & 3) << 1);
                        if (n < VOUT) {
                            size_t idx = (size_t)m * VOUT + n;
                            float2 om = *(const float2*)(mask + idx);
                            float2 bv = *(const float2*)(bias + n);
                            float l0 = acc[mi][ni][half * 2 + 0] + bv.x + __logf(om.x);
                            float l1 = acc[mi][ni][half * 2 + 1] + bv.y + __logf(om.y);
                            *(float2*)(out_logits + idx) = make_float2(l0, l1);
                            rmax = fmaxf(rmax, fmaxf(l0, l1));
                            if (om.x > 0.0f && n != 0 && g_winner[n] >= 0) can = 1;
                            if (om.y > 0.0f && g_winner[n + 1] >= 0) can = 1;
                        }
                    }
                    rmax = fmaxf(rmax, __shfl_xor_sync(0xFFFFFFFFu, rmax, 1));
                    rmax = fmaxf(rmax, __shfl_xor_sync(0xFFFFFFFFu, rmax, 2));
                    can |= __shfl_xor_sync(0xFFFFFFFFu, can, 1);
                    can |= __shfl_xor_sync(0xFFFFFFFFu, can, 2);
                    if ((lane & 3) == 0) {
                        atomicMax(&srmax[m], f2ord(rmax));
                        if (can) scan[m] = 1;
                    }
                }
            }
            asm volatile("bar.sync 1, 256;" ::: "memory");
            if (t < 128) {
                atomicMax(&g_rowmax[t], srmax[t]);
                if (scan[t]) g_cancopy[t] = 1;
                srmax[t] = 0u;
                scan[t] = 0;
            }
            asm volatile("bar.sync 1, 256;" ::: "memory");
        }
    }
}

// ---------------- K4: copy-or-generate gate ----------------------------------
__global__ void k_pog(const float* __restrict__ x,
                      const float* __restrict__ cogW,
                      const float* __restrict__ cogb,
                      float*       __restrict__ out_pog) {
    int b = blockIdx.x;
    int lane = threadIdx.x;
    float s0 = 0.f, s1 = 0.f;
    for (int k = lane; k < H; k += 32) {
        float xv = x[b * H + k];
        s0 += xv * cogW[k];
        s1 += xv * cogW[H + k];
    }
#pragma unroll
    for (int off = 16; off > 0; off >>= 1) {
        s0 += __shfl_xor_sync(0xFFFFFFFFu, s0, off);
        s1 += __shfl_xor_sync(0xFFFFFFFFu, s1, off);
    }
    if (lane == 0) {
        float l0 = s0 + cogb[0], l1 = s1 + cogb[1];
        int can = g_cancopy[b];
        float mx = can ? fmaxf(l0, l1) : l0;
        float e0 = expf(l0 - mx);
        float e1 = can ? expf(l1 - mx) : 0.0f;
        float inv = 1.0f / (e0 + e1);
        out_pog[2 * b]     = e0 * inv;
        out_pog[2 * b + 1] = e1 * inv;
    }
}

// ---------------- K5: row softmax over V_OUT + combine + log ------------------
__global__ __launch_bounds__(256) void k_final(float* __restrict__ logits_gen,
                                               float* __restrict__ out_probs,
                                               const float* __restrict__ pog) {
    int b = blockIdx.x;
    float mx = ord2f(g_rowmax[b]);
    __shared__ float red[256];
    const float* lrow = logits_gen + (size_t)b * VOUT;

    float sum = 0.0f;
    for (int n = threadIdx.x; n < VOUT; n += 256) sum += expf(lrow[n] - mx);
    red[threadIdx.x] = sum; __syncthreads();
    for (int off = 128; off > 0; off >>= 1) {
        if (threadIdx.x < off) red[threadIdx.x] += red[threadIdx.x + off];
        __syncthreads();
    }
    sum = red[0];
    float inv = 1.0f / sum;
    float pg = pog[2 * b], pc = pog[2 * b + 1];

    for (int n = threadIdx.x; n < VOUT; n += 256) {
        float p = expf(lrow[n] - mx) * inv;
        int w = g_winner[n];
        float ptr = (w >= 0) ? g_inpdist[(size_t)b * VIN + w] : 0.0f;
        out_probs[(size_t)b * VOUT + n] = logf(pg * p + pc * ptr);
        logits_gen[(size_t)b * VOUT + n] = p;
    }
}

// ---------------- launch ------------------------------------------------------
extern "C" void kernel_launch(void* const* d_in, const int* in_sizes, int n_in,
                              void* d_out, int out_size) {
    const float* x          = (const float*)d_in[0];
    const int*   inptensor  = (const int*)  d_in[1];
    const float* attn       = (const float*)d_in[2];
    const float* out_mask   = (const float*)d_in[3];
    const float* gen_W      = (const float*)d_in[4];
    const float* gen_b      = (const float*)d_in[5];
    const float* cog_W      = (const float*)d_in[6];
    const float* cog_b      = (const float*)d_in[7];
    const int*   inp_to_act = (const int*)  d_in[8];

    float* out = (float*)d_out;
    float* o_outprobs = out;
    float* o_pog      = out + (size_t)B * VOUT;
    float* o_gen      = o_pog + 2 * B;
    float* o_attn     = o_gen + (size_t)B * VOUT;

    cudaFuncSetAttribute(k_gemm, cudaFuncAttributeMaxDynamicSharedMemorySize, SMEM_TOTAL);

    k_init<<<1024, 256>>>();
    k_xcvt<<<(B * H / 4 + 255) / 256, 256>>>(x);
    k_winner<<<(VIN + 255) / 256, 256>>>(inp_to_act);
    k_attn<<<B, 256>>>(attn, inptensor, o_attn);
    k_gemm<<<GRID, NTHREADS, SMEM_TOTAL>>>(gen_W, gen_b, out_mask, o_gen);
    k_pog<<<B, 32>>>(x, cog_W, cog_b, o_pog);
    k_final<<<B, 256>>>(o_gen, o_outprobs, o_pog);
}

// round 8
// speedup vs baseline: 3.3041x; 1.5318x over previous
#include <cuda_runtime.h>
#include <cuda_fp16.h>
#include <stdint.h>
#include <math.h>

#define B    128
#define H    1024
#define S    512
#define VOUT 50000
#define VIN  32000

#define NTILE  128
#define KC     32
#define NCH    (H / KC)            // 32 chunks per tile
#define NT     ((VOUT + NTILE - 1) / NTILE)   // 391 tiles
#define GRID   148

#define NTHREADS 384               // warps 0-7 consumers, 8-11 producers

// smem stage = 2 tiles (XH, WH), each 128 rows x 80B
#define ROWB    80
#define TILE_B  (128 * ROWB)       // 10240
#define XH      0
#define WH      (1 * TILE_B)
#define STAGE_B (2 * TILE_B)       // 20480
#define NSTAGE  8
#define TILES_OFF 1024
#define RED_OFF  (TILES_OFF + NSTAGE * STAGE_B)   // 164864
#define CAN_OFF  (RED_OFF + 512)
#define SMEM_TOTAL (CAN_OFF + 512)                // 165888

// ---------------- persistent device scratch ----------------------------------
__device__ float        g_inpdist[B * VIN];
__device__ int          g_winner[VOUT];
__device__ unsigned int g_rowmax[B];
__device__ int          g_cancopy[B];
__device__ float        g_expsum[B];
__device__ __half       g_xh[B * H];

__device__ __forceinline__ unsigned int f2ord(float f) {
    unsigned int u = __float_as_uint(f);
    return (u & 0x80000000u) ? ~u : (u | 0x80000000u);
}
__device__ __forceinline__ float ord2f(unsigned int e) {
    unsigned int u = (e & 0x80000000u) ? (e & 0x7FFFFFFFu) : ~e;
    return __uint_as_float(u);
}

__device__ __forceinline__ uint32_t smem_u32(const void* p) {
    uint32_t a;
    asm("{ .reg .u64 t; cvta.to.shared.u64 t, %1; cvt.u32.u64 %0, t; }" : "=r"(a) : "l"(p));
    return a;
}

#define MBARRIER_INIT(addr, cnt) \
    asm volatile("mbarrier.init.shared.b64 [%0], %1;" :: "r"(addr), "r"(cnt) : "memory")
#define MBARRIER_ARRIVE(addr) \
    asm volatile("mbarrier.arrive.shared.b64 _, [%0];" :: "r"(addr) : "memory")
#define MBARRIER_WAIT_PARITY(mbar_addr, phase) do {                                  \
    uint32_t _mb = (uint32_t)(mbar_addr);                                            \
    uint32_t _ph = (uint32_t)(phase);                                                \
    asm volatile(                                                                    \
        "{\n\t.reg .pred P1;\n\t"                                                    \
        "WAIT_LOOP_%=:\n\t"                                                          \
        "mbarrier.try_wait.parity.acquire.cta.shared::cta.b64 P1, [%0], %1, 0x989680;\n\t" \
        "@P1 bra.uni WAIT_DONE_%=;\n\t"                                              \
        "bra.uni WAIT_LOOP_%=;\n\t"                                                  \
        "WAIT_DONE_%=:\n\t}"                                                         \
        :: "r"(_mb), "r"(_ph) : "memory");                                           \
} while (0)

__device__ __forceinline__ void ldm4(uint32_t addr, uint32_t& r0, uint32_t& r1,
                                     uint32_t& r2, uint32_t& r3) {
    asm volatile("ldmatrix.sync.aligned.m8n8.x4.shared.b16 {%0,%1,%2,%3}, [%4];"
                 : "=r"(r0), "=r"(r1), "=r"(r2), "=r"(r3) : "r"(addr));
}
__device__ __forceinline__ uint32_t ldm_addr(uint32_t tile, int base_row, int k16, int lane) {
    int mat = lane >> 3;
    int row = base_row + (lane & 7) + ((mat & 1) << 3);
    int ke  = k16 + ((mat >> 1) << 3);
    return tile + row * ROWB + ke * 2;
}
__device__ __forceinline__ void mma_f16(float* c, const uint32_t* a, uint32_t b0, uint32_t b1) {
    asm volatile(
        "mma.sync.aligned.m16n8k16.row.col.f32.f16.f16.f32 "
        "{%0,%1,%2,%3}, {%4,%5,%6,%7}, {%8,%9}, {%0,%1,%2,%3};"
        : "+f"(c[0]), "+f"(c[1]), "+f"(c[2]), "+f"(c[3])
        : "r"(a[0]), "r"(a[1]), "r"(a[2]), "r"(a[3]), "r"(b0), "r"(b1));
}

// ---------------- K0: reset scratch ------------------------------------------
__global__ void k_init() {
    int i = blockIdx.x * blockDim.x + threadIdx.x;
    int stride = gridDim.x * blockDim.x;
    for (int j = i; j < B * VIN; j += stride) g_inpdist[j] = 0.0f;
    for (int j = i; j < VOUT; j += stride)    g_winner[j]  = -1;
    if (i < B) { g_rowmax[i] = 0u; g_cancopy[i] = 0; g_expsum[i] = 0.0f; }
}

// ---------------- K0b: convert x -> fp16 (once, exact hi part) ---------------
__global__ void k_xcvt(const float* __restrict__ x) {
    int i = blockIdx.x * blockDim.x + threadIdx.x;   // per 4 floats
    if (i < B * H / 4) {
        float4 v = ((const float4*)x)[i];
        unsigned h0 = (unsigned)__half_as_ushort(__float2half_rn(v.x));
        unsigned h1 = (unsigned)__half_as_ushort(__float2half_rn(v.y));
        unsigned h2 = (unsigned)__half_as_ushort(__float2half_rn(v.z));
        unsigned h3 = (unsigned)__half_as_ushort(__float2half_rn(v.w));
        ((uint2*)g_xh)[i] = make_uint2(h0 | (h1 << 16), h2 | (h3 << 16));
    }
}

// ---------------- K1: attention softmax + scatter-add ------------------------
__global__ __launch_bounds__(256) void k_attn(const float* __restrict__ attn,
                                              const int*   __restrict__ inptok,
                                              float*       __restrict__ out_attn) {
    int b = blockIdx.x;
    __shared__ float red[256];
    const float* row = attn + b * S;

    float mx = -INFINITY;
    for (int s = threadIdx.x; s < S; s += 256) mx = fmaxf(mx, row[s]);
    red[threadIdx.x] = mx; __syncthreads();
    for (int off = 128; off > 0; off >>= 1) {
        if (threadIdx.x < off) red[threadIdx.x] = fmaxf(red[threadIdx.x], red[threadIdx.x + off]);
        __syncthreads();
    }
    mx = red[0]; __syncthreads();

    float sum = 0.0f;
    for (int s = threadIdx.x; s < S; s += 256) sum += expf(row[s] - mx);
    red[threadIdx.x] = sum; __syncthreads();
    for (int off = 128; off > 0; off >>= 1) {
        if (threadIdx.x < off) red[threadIdx.x] += red[threadIdx.x + off];
        __syncthreads();
    }
    sum = red[0];
    float inv = 1.0f / sum;

    for (int s = threadIdx.x; s < S; s += 256) {
        float p = expf(row[s] - mx) * inv;
        out_attn[b * S + s] = p;
        atomicAdd(&g_inpdist[b * VIN + inptok[b * S + s]], p);
    }
}

// ---------------- K2: winner index -------------------------------------------
__global__ void k_winner(const int* __restrict__ inp_to_act) {
    int j = blockIdx.x * blockDim.x + threadIdx.x;
    if (j < VIN) atomicMax(&g_winner[inp_to_act[j]], j);
}

// ---------------- K3: warp-specialized persistent GEMM (single-pass fp16) ----
__global__ __launch_bounds__(NTHREADS, 1) void k_gemm(const float* __restrict__ W,
                                                      const float* __restrict__ bias,
                                                      const float* __restrict__ mask,
                                                      float*       __restrict__ out_logits) {
    extern __shared__ char smem[];
    uint32_t sb = smem_u32(smem);
    int t = threadIdx.x;
    int lane = t & 31;
    int wid = t >> 5;
    uint32_t* srmax = (uint32_t*)(smem + RED_OFF);
    int*      scan  = (int*)(smem + CAN_OFF);

    if (t == 0) {
#pragma unroll
        for (int s = 0; s < NSTAGE; s++) {
            MBARRIER_INIT(sb + s * 16,     128);   // full[s]: 128 producer threads
            MBARRIER_INIT(sb + s * 16 + 8, 256);   // empty[s]: 256 consumer threads
        }
    }
    if (t < 128) { srmax[t] = 0u; scan[t] = 0; }
    __syncthreads();

    if (t >= 256) {
        // ================= producers (warps 8-11) =================
        int pt = t - 256;
        int sc = 0, ph = 1;
        for (int tile = blockIdx.x; tile < NT; tile += GRID) {
            int n0 = tile * NTILE;
            for (int c = 0; c < NCH; c++) {
                MBARRIER_WAIT_PARITY(sb + sc * 16 + 8, ph);
                uint32_t buf = sb + TILES_OFF + sc * STAGE_B;
                int k0 = c * KC;
                // x tile: thread pt copies row pt (fp16, preconverted)
                {
                    const uint4* xh4 = (const uint4*)(g_xh + pt * H + k0);
                    uint32_t ro = buf + XH + pt * ROWB;
#pragma unroll
                    for (int j = 0; j < 4; j++) {
                        uint4 v = xh4[j];
                        asm volatile("st.shared.v4.b32 [%0], {%1,%2,%3,%4};"
                                     :: "r"(ro + j * 16),
                                        "r"(v.x), "r"(v.y), "r"(v.z), "r"(v.w) : "memory");
                    }
                }
                // W tile: convert fp32 -> fp16
#pragma unroll
                for (int i = 0; i < 8; i++) {
                    int g = pt + i * 128;
                    int row = g >> 3, k4 = (g & 7) << 2;
                    int nb = n0 + row;
                    float4 wv = (nb < VOUT)
                        ? *(const float4*)(W + (size_t)nb * H + k0 + k4)
                        : make_float4(0.f, 0.f, 0.f, 0.f);
                    unsigned h0 = (unsigned)__half_as_ushort(__float2half_rn(wv.x));
                    unsigned h1 = (unsigned)__half_as_ushort(__float2half_rn(wv.y));
                    unsigned h2 = (unsigned)__half_as_ushort(__float2half_rn(wv.z));
                    unsigned h3 = (unsigned)__half_as_ushort(__float2half_rn(wv.w));
                    unsigned a = h0 | (h1 << 16), b = h2 | (h3 << 16);
                    asm volatile("st.shared.v2.b32 [%0], {%1,%2};"
                                 :: "r"(buf + WH + row * ROWB + k4 * 2),
                                    "r"(a), "r"(b) : "memory");
                }
                MBARRIER_ARRIVE(sb + sc * 16);
                if (++sc == NSTAGE) { sc = 0; ph ^= 1; }
            }
        }
    } else {
        // ================= consumers (warps 0-7) =================
        int wm = (wid >> 2) * 64;
        int wn = (wid & 3) * 32;
        int sc = 0, ph = 0;

        for (int tile = blockIdx.x; tile < NT; tile += GRID) {
            int n0 = tile * NTILE;
            float acc[4][4][4];
#pragma unroll
            for (int mi = 0; mi < 4; mi++)
#pragma unroll
                for (int ni = 0; ni < 4; ni++)
#pragma unroll
                    for (int r = 0; r < 4; r++) acc[mi][ni][r] = 0.0f;

            for (int c = 0; c < NCH; c++) {
                MBARRIER_WAIT_PARITY(sb + sc * 16, ph);
                uint32_t buf = sb + TILES_OFF + sc * STAGE_B;
#pragma unroll
                for (int k16e = 0; k16e < 2; k16e++) {
                    int k16 = k16e * 16;
                    uint32_t bh[4][2];
                    {
                        uint32_t q0, q1, q2, q3;
                        ldm4(ldm_addr(buf + WH, wn,      k16, lane), q0, q1, q2, q3);
                        bh[0][0] = q0; bh[1][0] = q1; bh[0][1] = q2; bh[1][1] = q3;
                        ldm4(ldm_addr(buf + WH, wn + 16, k16, lane), q0, q1, q2, q3);
                        bh[2][0] = q0; bh[3][0] = q1; bh[2][1] = q2; bh[3][1] = q3;
                    }
                    uint32_t ah[4][4];
#pragma unroll
                    for (int mi = 0; mi < 4; mi++)
                        ldm4(ldm_addr(buf + XH, wm + mi * 16, k16, lane),
                             ah[mi][0], ah[mi][1], ah[mi][2], ah[mi][3]);
                    // 16 independent MMAs per acc reuse window
#pragma unroll
                    for (int mi = 0; mi < 4; mi++)
#pragma unroll
                        for (int ni = 0; ni < 4; ni++)
                            mma_f16(acc[mi][ni], ah[mi], bh[ni][0], bh[ni][1]);
                }
                MBARRIER_ARRIVE(sb + sc * 16 + 8);
                if (++sc == NSTAGE) { sc = 0; ph ^= 1; }
            }

            // ---- per-tile epilogue (consumers only) ----
#pragma unroll
            for (int mi = 0; mi < 4; mi++) {
#pragma unroll
                for (int half = 0; half < 2; half++) {
                    int m = wm + mi * 16 + (lane >> 2) + half * 8;
                    float rmax = -INFINITY;
                    int can = 0;
#pragma unroll
                    for (int ni = 0; ni < 4; ni++) {
                        int n = n0 + wn + ni * 8 + ((lane & 3) << 1);
                        if (n < VOUT) {
                            size_t idx = (size_t)m * VOUT + n;
                            float2 om = *(const float2*)(mask + idx);
                            float2 bv = *(const float2*)(bias + n);
                            float l0 = acc[mi][ni][half * 2 + 0] + bv.x + __logf(om.x);
                            float l1 = acc[mi][ni][half * 2 + 1] + bv.y + __logf(om.y);
                            *(float2*)(out_logits + idx) = make_float2(l0, l1);
                            rmax = fmaxf(rmax, fmaxf(l0, l1));
                            if (om.x > 0.0f && n != 0 && g_winner[n] >= 0) can = 1;
                            if (om.y > 0.0f && g_winner[n + 1] >= 0) can = 1;
                        }
                    }
                    rmax = fmaxf(rmax, __shfl_xor_sync(0xFFFFFFFFu, rmax, 1));
                    rmax = fmaxf(rmax, __shfl_xor_sync(0xFFFFFFFFu, rmax, 2));
                    can |= __shfl_xor_sync(0xFFFFFFFFu, can, 1);
                    can |= __shfl_xor_sync(0xFFFFFFFFu, can, 2);
                    if ((lane & 3) == 0) {
                        atomicMax(&srmax[m], f2ord(rmax));
                        if (can) scan[m] = 1;
                    }
                }
            }
            asm volatile("bar.sync 1, 256;" ::: "memory");
            if (t < 128) {
                atomicMax(&g_rowmax[t], srmax[t]);
                if (scan[t]) g_cancopy[t] = 1;
                srmax[t] = 0u;
                scan[t] = 0;
            }
            asm volatile("bar.sync 1, 256;" ::: "memory");
        }
    }
}

// ---------------- K4: copy-or-generate gate ----------------------------------
__global__ void k_pog(const float* __restrict__ x,
                      const float* __restrict__ cogW,
                      const float* __restrict__ cogb,
                      float*       __restrict__ out_pog) {
    int b = blockIdx.x;
    int lane = threadIdx.x;
    float s0 = 0.f, s1 = 0.f;
    for (int k = lane; k < H; k += 32) {
        float xv = x[b * H + k];
        s0 += xv * cogW[k];
        s1 += xv * cogW[H + k];
    }
#pragma unroll
    for (int off = 16; off > 0; off >>= 1) {
        s0 += __shfl_xor_sync(0xFFFFFFFFu, s0, off);
        s1 += __shfl_xor_sync(0xFFFFFFFFu, s1, off);
    }
    if (lane == 0) {
        float l0 = s0 + cogb[0], l1 = s1 + cogb[1];
        int can = g_cancopy[b];
        float mx = can ? fmaxf(l0, l1) : l0;
        float e0 = expf(l0 - mx);
        float e1 = can ? expf(l1 - mx) : 0.0f;
        float inv = 1.0f / (e0 + e1);
        out_pog[2 * b]     = e0 * inv;
        out_pog[2 * b + 1] = e1 * inv;
    }
}

// ---------------- K5a: partial exp-sums over V_OUT ---------------------------
#define SUMSEG 8
__global__ __launch_bounds__(256) void k_sum(const float* __restrict__ logits) {
    int b = blockIdx.x;
    int seg = blockIdx.y;
    float mx = ord2f(g_rowmax[b]);
    const float* lrow = logits + (size_t)b * VOUT;
    int n0 = seg * (VOUT / SUMSEG);
    int n1 = n0 + (VOUT / SUMSEG);

    float sum = 0.0f;
    for (int n = n0 + threadIdx.x; n < n1; n += 256) sum += expf(lrow[n] - mx);
#pragma unroll
    for (int off = 16; off > 0; off >>= 1)
        sum += __shfl_xor_sync(0xFFFFFFFFu, sum, off);
    __shared__ float red[8];
    if ((threadIdx.x & 31) == 0) red[threadIdx.x >> 5] = sum;
    __syncthreads();
    if (threadIdx.x == 0) {
        float s = 0.0f;
#pragma unroll
        for (int w = 0; w < 8; w++) s += red[w];
        atomicAdd(&g_expsum[b], s);
    }
}

// ---------------- K5b: normalize + combine + log ------------------------------
#define NORMSEG 16
__global__ __launch_bounds__(256) void k_norm(float* __restrict__ logits_gen,
                                              float* __restrict__ out_probs,
                                              const float* __restrict__ pog) {
    int b = blockIdx.x;
    int seg = blockIdx.y;
    float mx = ord2f(g_rowmax[b]);
    float inv = 1.0f / g_expsum[b];
    float pg = pog[2 * b], pc = pog[2 * b + 1];
    const float* dist = g_inpdist + (size_t)b * VIN;
    int n0 = seg * (VOUT / NORMSEG);
    int n1 = n0 + (VOUT / NORMSEG);
    if (seg == NORMSEG - 1) n1 = VOUT;

    for (int n = n0 + threadIdx.x; n < n1; n += 256) {
        size_t idx = (size_t)b * VOUT + n;
        float p = expf(logits_gen[idx] - mx) * inv;
        int w = g_winner[n];
        float ptr = (w >= 0) ? dist[w] : 0.0f;
        out_probs[idx] = logf(pg * p + pc * ptr);
        logits_gen[idx] = p;
    }
}

// ---------------- launch ------------------------------------------------------
extern "C" void kernel_launch(void* const* d_in, const int* in_sizes, int n_in,
                              void* d_out, int out_size) {
    const float* x          = (const float*)d_in[0];
    const int*   inptensor  = (const int*)  d_in[1];
    const float* attn       = (const float*)d_in[2];
    const float* out_mask   = (const float*)d_in[3];
    const float* gen_W      = (const float*)d_in[4];
    const float* gen_b      = (const float*)d_in[5];
    const float* cog_W      = (const float*)d_in[6];
    const float* cog_b      = (const float*)d_in[7];
    const int*   inp_to_act = (const int*)  d_in[8];

    float* out = (float*)d_out;
    float* o_outprobs = out;
    float* o_pog      = out + (size_t)B * VOUT;
    float* o_gen      = o_pog + 2 * B;
    float* o_attn     = o_gen + (size_t)B * VOUT;

    cudaFuncSetAttribute(k_gemm, cudaFuncAttributeMaxDynamicSharedMemorySize, SMEM_TOTAL);

    k_init<<<1024, 256>>>();
    k_xcvt<<<(B * H / 4 + 255) / 256, 256>>>(x);
    k_winner<<<(VIN + 255) / 256, 256>>>(inp_to_act);
    k_attn<<<B, 256>>>(attn, inptensor, o_attn);
    k_gemm<<<GRID, NTHREADS, SMEM_TOTAL>>>(gen_W, gen_b, out_mask, o_gen);
    k_pog<<<B, 32>>>(x, cog_W, cog_b, o_pog);
    k_sum<<<dim3(B, SUMSEG), 256>>>(o_gen);
    k_norm<<<dim3(B, NORMSEG), 256>>>(o_gen, o_outprobs, o_pog);
}

// round 9
// speedup vs baseline: 3.3917x; 1.0265x over previous
#include <cuda_runtime.h>
#include <cuda_fp16.h>
#include <stdint.h>
#include <math.h>

#define B    128
#define H    1024
#define S    512
#define VOUT 50000
#define VIN  32000

#define NTILE  128
#define KC     32
#define NCH    (H / KC)            // 32 chunks per tile
#define NT     ((VOUT + NTILE - 1) / NTILE)   // 391 tiles
#define GRID   148

#define NTHREADS 384               // warps 0-7 consumers, 8-11 producers

// smem stage = 2 tiles (XH, WH), each 128 rows x 80B
#define ROWB    80
#define TILE_B  (128 * ROWB)       // 10240
#define XH      0
#define WH      (1 * TILE_B)
#define STAGE_B (2 * TILE_B)       // 20480
#define NSTAGE  8
#define TILES_OFF 1024
#define RED_OFF  (TILES_OFF + NSTAGE * STAGE_B)   // 164864: float ssum[128]
#define CAN_OFF  (RED_OFF + 512)
#define SMEM_TOTAL (CAN_OFF + 512)                // 165888

// ---------------- persistent device scratch ----------------------------------
__device__ float        g_inpdist[B * VIN];
__device__ int          g_winner[VOUT];
__device__ int          g_cancopy[B];
__device__ float        g_expsum[B];
__device__ __half       g_xh[B * H];

__device__ __forceinline__ uint32_t smem_u32(const void* p) {
    uint32_t a;
    asm("{ .reg .u64 t; cvta.to.shared.u64 t, %1; cvt.u32.u64 %0, t; }" : "=r"(a) : "l"(p));
    return a;
}

#define MBARRIER_INIT(addr, cnt) \
    asm volatile("mbarrier.init.shared.b64 [%0], %1;" :: "r"(addr), "r"(cnt) : "memory")
#define MBARRIER_ARRIVE(addr) \
    asm volatile("mbarrier.arrive.shared.b64 _, [%0];" :: "r"(addr) : "memory")
#define MBARRIER_WAIT_PARITY(mbar_addr, phase) do {                                  \
    uint32_t _mb = (uint32_t)(mbar_addr);                                            \
    uint32_t _ph = (uint32_t)(phase);                                                \
    asm volatile(                                                                    \
        "{\n\t.reg .pred P1;\n\t"                                                    \
        "WAIT_LOOP_%=:\n\t"                                                          \
        "mbarrier.try_wait.parity.acquire.cta.shared::cta.b64 P1, [%0], %1, 0x989680;\n\t" \
        "@P1 bra.uni WAIT_DONE_%=;\n\t"                                              \
        "bra.uni WAIT_LOOP_%=;\n\t"                                                  \
        "WAIT_DONE_%=:\n\t}"                                                         \
        :: "r"(_mb), "r"(_ph) : "memory");                                           \
} while (0)

__device__ __forceinline__ void ldm4(uint32_t addr, uint32_t& r0, uint32_t& r1,
                                     uint32_t& r2, uint32_t& r3) {
    asm volatile("ldmatrix.sync.aligned.m8n8.x4.shared.b16 {%0,%1,%2,%3}, [%4];"
                 : "=r"(r0), "=r"(r1), "=r"(r2), "=r"(r3) : "r"(addr));
}
__device__ __forceinline__ uint32_t ldm_addr(uint32_t tile, int base_row, int k16, int lane) {
    int mat = lane >> 3;
    int row = base_row + (lane & 7) + ((mat & 1) << 3);
    int ke  = k16 + ((mat >> 1) << 3);
    return tile + row * ROWB + ke * 2;
}
__device__ __forceinline__ void mma_f16(float* c, const uint32_t* a, uint32_t b0, uint32_t b1) {
    asm volatile(
        "mma.sync.aligned.m16n8k16.row.col.f32.f16.f16.f32 "
        "{%0,%1,%2,%3}, {%4,%5,%6,%7}, {%8,%9}, {%0,%1,%2,%3};"
        : "+f"(c[0]), "+f"(c[1]), "+f"(c[2]), "+f"(c[3])
        : "r"(a[0]), "r"(a[1]), "r"(a[2]), "r"(a[3]), "r"(b0), "r"(b1));
}

// ---------------- K0: reset scratch ------------------------------------------
__global__ void k_init() {
    int i = blockIdx.x * blockDim.x + threadIdx.x;
    int stride = gridDim.x * blockDim.x;
    for (int j = i; j < B * VIN; j += stride) g_inpdist[j] = 0.0f;
    for (int j = i; j < VOUT; j += stride)    g_winner[j]  = -1;
    if (i < B) { g_cancopy[i] = 0; g_expsum[i] = 0.0f; }
}

// ---------------- K0b: convert x -> fp16 (once) -------------------------------
__global__ void k_xcvt(const float* __restrict__ x) {
    int i = blockIdx.x * blockDim.x + threadIdx.x;   // per 4 floats
    if (i < B * H / 4) {
        float4 v = ((const float4*)x)[i];
        unsigned h0 = (unsigned)__half_as_ushort(__float2half_rn(v.x));
        unsigned h1 = (unsigned)__half_as_ushort(__float2half_rn(v.y));
        unsigned h2 = (unsigned)__half_as_ushort(__float2half_rn(v.z));
        unsigned h3 = (unsigned)__half_as_ushort(__float2half_rn(v.w));
        ((uint2*)g_xh)[i] = make_uint2(h0 | (h1 << 16), h2 | (h3 << 16));
    }
}

// ---------------- K1: attention softmax + scatter-add ------------------------
__global__ __launch_bounds__(256) void k_attn(const float* __restrict__ attn,
                                              const int*   __restrict__ inptok,
                                              float*       __restrict__ out_attn) {
    int b = blockIdx.x;
    __shared__ float red[256];
    const float* row = attn + b * S;

    float mx = -INFINITY;
    for (int s = threadIdx.x; s < S; s += 256) mx = fmaxf(mx, row[s]);
    red[threadIdx.x] = mx; __syncthreads();
    for (int off = 128; off > 0; off >>= 1) {
        if (threadIdx.x < off) red[threadIdx.x] = fmaxf(red[threadIdx.x], red[threadIdx.x + off]);
        __syncthreads();
    }
    mx = red[0]; __syncthreads();

    float sum = 0.0f;
    for (int s = threadIdx.x; s < S; s += 256) sum += __expf(row[s] - mx);
    red[threadIdx.x] = sum; __syncthreads();
    for (int off = 128; off > 0; off >>= 1) {
        if (threadIdx.x < off) red[threadIdx.x] += red[threadIdx.x + off];
        __syncthreads();
    }
    sum = red[0];
    float inv = 1.0f / sum;

    for (int s = threadIdx.x; s < S; s += 256) {
        float p = __expf(row[s] - mx) * inv;
        out_attn[b * S + s] = p;
        atomicAdd(&g_inpdist[b * VIN + inptok[b * S + s]], p);
    }
}

// ---------------- K2: winner index -------------------------------------------
__global__ void k_winner(const int* __restrict__ inp_to_act) {
    int j = blockIdx.x * blockDim.x + threadIdx.x;
    if (j < VIN) atomicMax(&g_winner[inp_to_act[j]], j);
}

// ---------------- K3: warp-specialized persistent GEMM + exp epilogue --------
// writes e = exp(x.W + b) * mask into out_e; accumulates g_expsum per row
__global__ __launch_bounds__(NTHREADS, 1) void k_gemm(const float* __restrict__ W,
                                                      const float* __restrict__ bias,
                                                      const float* __restrict__ mask,
                                                      float*       __restrict__ out_e) {
    extern __shared__ char smem[];
    uint32_t sb = smem_u32(smem);
    int t = threadIdx.x;
    int lane = t & 31;
    int wid = t >> 5;
    float* ssum = (float*)(smem + RED_OFF);
    int*   scan = (int*)(smem + CAN_OFF);

    if (t == 0) {
#pragma unroll
        for (int s = 0; s < NSTAGE; s++) {
            MBARRIER_INIT(sb + s * 16,     128);   // full[s]: 128 producer threads
            MBARRIER_INIT(sb + s * 16 + 8, 256);   // empty[s]: 256 consumer threads
        }
    }
    if (t < 128) { ssum[t] = 0.0f; scan[t] = 0; }
    __syncthreads();

    if (t >= 256) {
        // ================= producers (warps 8-11) =================
        int pt = t - 256;
        int sc = 0, ph = 1;
        for (int tile = blockIdx.x; tile < NT; tile += GRID) {
            int n0 = tile * NTILE;
            for (int c = 0; c < NCH; c++) {
                MBARRIER_WAIT_PARITY(sb + sc * 16 + 8, ph);
                uint32_t buf = sb + TILES_OFF + sc * STAGE_B;
                int k0 = c * KC;
                // x tile: thread pt copies row pt (fp16, preconverted)
                {
                    const uint4* xh4 = (const uint4*)(g_xh + pt * H + k0);
                    uint32_t ro = buf + XH + pt * ROWB;
#pragma unroll
                    for (int j = 0; j < 4; j++) {
                        uint4 v = xh4[j];
                        asm volatile("st.shared.v4.b32 [%0], {%1,%2,%3,%4};"
                                     :: "r"(ro + j * 16),
                                        "r"(v.x), "r"(v.y), "r"(v.z), "r"(v.w) : "memory");
                    }
                }
                // W tile: convert fp32 -> fp16
#pragma unroll
                for (int i = 0; i < 8; i++) {
                    int g = pt + i * 128;
                    int row = g >> 3, k4 = (g & 7) << 2;
                    int nb = n0 + row;
                    float4 wv = (nb < VOUT)
                        ? *(const float4*)(W + (size_t)nb * H + k0 + k4)
                        : make_float4(0.f, 0.f, 0.f, 0.f);
                    unsigned h0 = (unsigned)__half_as_ushort(__float2half_rn(wv.x));
                    unsigned h1 = (unsigned)__half_as_ushort(__float2half_rn(wv.y));
                    unsigned h2 = (unsigned)__half_as_ushort(__float2half_rn(wv.z));
                    unsigned h3 = (unsigned)__half_as_ushort(__float2half_rn(wv.w));
                    unsigned a = h0 | (h1 << 16), b = h2 | (h3 << 16);
                    asm volatile("st.shared.v2.b32 [%0], {%1,%2};"
                                 :: "r"(buf + WH + row * ROWB + k4 * 2),
                                    "r"(a), "r"(b) : "memory");
                }
                MBARRIER_ARRIVE(sb + sc * 16);
                if (++sc == NSTAGE) { sc = 0; ph ^= 1; }
            }
        }
    } else {
        // ================= consumers (warps 0-7) =================
        int wm = (wid >> 2) * 64;
        int wn = (wid & 3) * 32;
        int sc = 0, ph = 0;

        for (int tile = blockIdx.x; tile < NT; tile += GRID) {
            int n0 = tile * NTILE;
            float acc[4][4][4];
#pragma unroll
            for (int mi = 0; mi < 4; mi++)
#pragma unroll
                for (int ni = 0; ni < 4; ni++)
#pragma unroll
                    for (int r = 0; r < 4; r++) acc[mi][ni][r] = 0.0f;

            for (int c = 0; c < NCH; c++) {
                MBARRIER_WAIT_PARITY(sb + sc * 16, ph);
                uint32_t buf = sb + TILES_OFF + sc * STAGE_B;
#pragma unroll
                for (int k16e = 0; k16e < 2; k16e++) {
                    int k16 = k16e * 16;
                    uint32_t bh[4][2];
                    {
                        uint32_t q0, q1, q2, q3;
                        ldm4(ldm_addr(buf + WH, wn,      k16, lane), q0, q1, q2, q3);
                        bh[0][0] = q0; bh[1][0] = q1; bh[0][1] = q2; bh[1][1] = q3;
                        ldm4(ldm_addr(buf + WH, wn + 16, k16, lane), q0, q1, q2, q3);
                        bh[2][0] = q0; bh[3][0] = q1; bh[2][1] = q2; bh[3][1] = q3;
                    }
                    uint32_t ah[4][4];
#pragma unroll
                    for (int mi = 0; mi < 4; mi++)
                        ldm4(ldm_addr(buf + XH, wm + mi * 16, k16, lane),
                             ah[mi][0], ah[mi][1], ah[mi][2], ah[mi][3]);
#pragma unroll
                    for (int mi = 0; mi < 4; mi++)
#pragma unroll
                        for (int ni = 0; ni < 4; ni++)
                            mma_f16(acc[mi][ni], ah[mi], bh[ni][0], bh[ni][1]);
                }
                MBARRIER_ARRIVE(sb + sc * 16 + 8);
                if (++sc == NSTAGE) { sc = 0; ph ^= 1; }
            }

            // ---- per-tile epilogue: e = exp(acc + bias) * mask ----
#pragma unroll
            for (int mi = 0; mi < 4; mi++) {
#pragma unroll
                for (int half = 0; half < 2; half++) {
                    int m = wm + mi * 16 + (lane >> 2) + half * 8;
                    float psum = 0.0f;
                    int can = 0;
#pragma unroll
                    for (int ni = 0; ni < 4; ni++) {
                        int n = n0 + wn + ni * 8 + ((lane & 3) << 1);
                        if (n < VOUT) {
                            size_t idx = (size_t)m * VOUT + n;
                            float2 om = *(const float2*)(mask + idx);
                            float2 bv = *(const float2*)(bias + n);
                            float e0 = __expf(acc[mi][ni][half * 2 + 0] + bv.x) * om.x;
                            float e1 = __expf(acc[mi][ni][half * 2 + 1] + bv.y) * om.y;
                            *(float2*)(out_e + idx) = make_float2(e0, e1);
                            psum += e0 + e1;
                            if (om.x > 0.0f && n != 0 && g_winner[n] >= 0) can = 1;
                            if (om.y > 0.0f && g_winner[n + 1] >= 0) can = 1;
                        }
                    }
                    psum += __shfl_xor_sync(0xFFFFFFFFu, psum, 1);
                    psum += __shfl_xor_sync(0xFFFFFFFFu, psum, 2);
                    can |= __shfl_xor_sync(0xFFFFFFFFu, can, 1);
                    can |= __shfl_xor_sync(0xFFFFFFFFu, can, 2);
                    if ((lane & 3) == 0) {
                        atomicAdd(&ssum[m], psum);
                        if (can) scan[m] = 1;
                    }
                }
            }
            asm volatile("bar.sync 1, 256;" ::: "memory");
            if (t < 128) {
                atomicAdd(&g_expsum[t], ssum[t]);
                if (scan[t]) g_cancopy[t] = 1;
                ssum[t] = 0.0f;
                scan[t] = 0;
            }
            asm volatile("bar.sync 1, 256;" ::: "memory");
        }
    }
}

// ---------------- K4: copy-or-generate gate ----------------------------------
__global__ void k_pog(const float* __restrict__ x,
                      const float* __restrict__ cogW,
                      const float* __restrict__ cogb,
                      float*       __restrict__ out_pog) {
    int b = blockIdx.x;
    int lane = threadIdx.x;
    float s0 = 0.f, s1 = 0.f;
    for (int k = lane; k < H; k += 32) {
        float xv = x[b * H + k];
        s0 += xv * cogW[k];
        s1 += xv * cogW[H + k];
    }
#pragma unroll
    for (int off = 16; off > 0; off >>= 1) {
        s0 += __shfl_xor_sync(0xFFFFFFFFu, s0, off);
        s1 += __shfl_xor_sync(0xFFFFFFFFu, s1, off);
    }
    if (lane == 0) {
        float l0 = s0 + cogb[0], l1 = s1 + cogb[1];
        int can = g_cancopy[b];
        float mx = can ? fmaxf(l0, l1) : l0;
        float e0 = expf(l0 - mx);
        float e1 = can ? expf(l1 - mx) : 0.0f;
        float inv = 1.0f / (e0 + e1);
        out_pog[2 * b]     = e0 * inv;
        out_pog[2 * b + 1] = e1 * inv;
    }
}

// ---------------- K5: normalize + combine + log -------------------------------
#define NORMSEG 16
__global__ __launch_bounds__(256) void k_norm(float* __restrict__ e_gen,
                                              float* __restrict__ out_probs,
                                              const float* __restrict__ pog) {
    int b = blockIdx.x;
    int seg = blockIdx.y;
    float inv = 1.0f / g_expsum[b];
    float pg = pog[2 * b], pc = pog[2 * b + 1];
    const float* dist = g_inpdist + (size_t)b * VIN;
    int n0 = seg * (VOUT / NORMSEG);
    int n1 = n0 + (VOUT / NORMSEG);
    if (seg == NORMSEG - 1) n1 = VOUT;

    for (int n = n0 + threadIdx.x; n < n1; n += 256) {
        size_t idx = (size_t)b * VOUT + n;
        float p = e_gen[idx] * inv;
        int w = g_winner[n];
        float ptr = (w >= 0) ? dist[w] : 0.0f;
        out_probs[idx] = __logf(pg * p + pc * ptr);
        e_gen[idx] = p;
    }
}

// ---------------- launch ------------------------------------------------------
extern "C" void kernel_launch(void* const* d_in, const int* in_sizes, int n_in,
                              void* d_out, int out_size) {
    const float* x          = (const float*)d_in[0];
    const int*   inptensor  = (const int*)  d_in[1];
    const float* attn       = (const float*)d_in[2];
    const float* out_mask   = (const float*)d_in[3];
    const float* gen_W      = (const float*)d_in[4];
    const float* gen_b      = (const float*)d_in[5];
    const float* cog_W      = (const float*)d_in[6];
    const float* cog_b      = (const float*)d_in[7];
    const int*   inp_to_act = (const int*)  d_in[8];

    float* out = (float*)d_out;
    float* o_outprobs = out;
    float* o_pog      = out + (size_t)B * VOUT;
    float* o_gen      = o_pog + 2 * B;
    float* o_attn     = o_gen + (size_t)B * VOUT;

    cudaFuncSetAttribute(k_gemm, cudaFuncAttributeMaxDynamicSharedMemorySize, SMEM_TOTAL);

    k_init<<<1024, 256>>>();
    k_xcvt<<<(B * H / 4 + 255) / 256, 256>>>(x);
    k_winner<<<(VIN + 255) / 256, 256>>>(inp_to_act);
    k_attn<<<B, 256>>>(attn, inptensor, o_attn);
    k_gemm<<<GRID, NTHREADS, SMEM_TOTAL>>>(gen_W, gen_b, out_mask, o_gen);
    k_pog<<<B, 32>>>(x, cog_W, cog_b, o_pog);
    k_norm<<<dim3(B, NORMSEG), 256>>>(o_gen, o_outprobs, o_pog);
}